// round 1
// baseline (speedup 1.0000x reference)
#include <cuda_runtime.h>
#include <math.h>

#define B_SZ    32
#define L_SZ    2048
#define NROWS   (B_SZ*L_SZ)      /* 65536 */
#define DMODEL  256
#define DINNER  512
#define NH      8
#define HD      64
#define DSTATE  64
#define CHUNK   64
#define NC      (L_SZ/CHUNK)     /* 32 */
#define CONVD   640
#define DPROJ   1160
#define DFFN    1024

/* ------------------------------------------------------------------ */
/* Scratch (device globals; no allocation allowed)                     */
/* ------------------------------------------------------------------ */
__device__ float g_zxbcdt[(size_t)NROWS*DPROJ];           /* 304 MB */
__device__ float g_xbc[(size_t)NROWS*CONVD];              /* post-conv silu */
__device__ float g_dtsp[(size_t)NROWS*NH];
__device__ float g_acs[(size_t)B_SZ*NH*L_SZ];             /* per-chunk cumsum */
__device__ float g_cdec[B_SZ*NH*NC];
__device__ float g_states[(size_t)B_SZ*NC*NH*HD*DSTATE];
__device__ float g_prev[(size_t)B_SZ*NC*NH*HD*DSTATE];
__device__ float g_y[(size_t)NROWS*DINNER];
__device__ float g_yn[(size_t)NROWS*DINNER];
__device__ float g_t256[(size_t)NROWS*DMODEL];
__device__ float g_hidden[(size_t)NROWS*DMODEL];
__device__ float g_h1[(size_t)NROWS*DFFN];

/* ------------------------------------------------------------------ */
/* SGEMM: C[M,N] = A[M,K] @ W[N,K]^T + bias, optional hardswish        */
/* BM=BN=128, BK=8, 256 threads, 8x8 per thread.                       */
/* M multiple of 128, K multiple of 8; N bounds-checked.               */
/* ------------------------------------------------------------------ */
__global__ void sgemm_bias(const float* __restrict__ A, const float* __restrict__ W,
                           const float* __restrict__ bias, float* __restrict__ C,
                           int M, int N, int K, int act)
{
    __shared__ float As[8][128];
    __shared__ float Bs[8][128];
    int tid  = threadIdx.x;
    int m0   = blockIdx.y * 128;
    int n0   = blockIdx.x * 128;
    int arow = tid >> 1;            /* 0..127 */
    int acol = (tid & 1) * 4;       /* 0 or 4 */
    int trow = (tid >> 4) * 8;
    int tcol = (tid & 15) * 8;

    float acc[8][8];
#pragma unroll
    for (int i = 0; i < 8; i++)
#pragma unroll
        for (int j = 0; j < 8; j++) acc[i][j] = 0.f;

    const float* Aptr = A + (size_t)(m0 + arow) * K + acol;
    int wr = n0 + arow; bool wvalid = wr < N; if (wr >= N) wr = N - 1;
    const float* Wptr = W + (size_t)wr * K + acol;

    for (int k0 = 0; k0 < K; k0 += 8) {
        float4 av = *(const float4*)(Aptr + k0);
        float4 wv = wvalid ? *(const float4*)(Wptr + k0) : make_float4(0.f,0.f,0.f,0.f);
        As[acol+0][arow] = av.x; As[acol+1][arow] = av.y;
        As[acol+2][arow] = av.z; As[acol+3][arow] = av.w;
        Bs[acol+0][arow] = wv.x; Bs[acol+1][arow] = wv.y;
        Bs[acol+2][arow] = wv.z; Bs[acol+3][arow] = wv.w;
        __syncthreads();
#pragma unroll
        for (int kk = 0; kk < 8; kk++) {
            float ra[8], rb[8];
#pragma unroll
            for (int i = 0; i < 8; i++) ra[i] = As[kk][trow + i];
#pragma unroll
            for (int j = 0; j < 8; j++) rb[j] = Bs[kk][tcol + j];
#pragma unroll
            for (int i = 0; i < 8; i++)
#pragma unroll
                for (int j = 0; j < 8; j++) acc[i][j] += ra[i] * rb[j];
        }
        __syncthreads();
    }

#pragma unroll
    for (int i = 0; i < 8; i++) {
        int gm = m0 + trow + i;
#pragma unroll
        for (int j = 0; j < 8; j++) {
            int gn = n0 + tcol + j;
            if (gn < N) {
                float v = acc[i][j] + bias[gn];
                if (act == 1) {                 /* hardswish */
                    float t = fminf(fmaxf(v + 3.f, 0.f), 6.f);
                    v = v * t * (1.f / 6.f);
                }
                C[(size_t)gm * N + gn] = v;
            }
        }
    }
}

/* ------------------------------------------------------------------ */
/* Causal conv (K=4) + SiLU over the xBC slice of zxbcdt               */
/* ------------------------------------------------------------------ */
__global__ void conv_kernel(const float* __restrict__ w, const float* __restrict__ cb)
{
    int idx = blockIdx.x * blockDim.x + threadIdx.x;
    if (idx >= NROWS * CONVD) return;
    int ch = idx % CONVD;
    int r  = idx / CONVD;
    int l  = r % L_SZ;
    int b  = r / L_SZ;
    float acc = cb[ch];
#pragma unroll
    for (int k = 0; k < 4; k++) {
        int ls = l + k - 3;
        if (ls >= 0)
            acc += g_zxbcdt[(size_t)(b * L_SZ + ls) * DPROJ + DINNER + ch] * w[ch * 4 + k];
    }
    acc = acc / (1.f + __expf(-acc));  /* silu */
    g_xbc[idx] = acc;
}

/* softplus(dt + dt_bias) */
__global__ void dtsp_kernel(const float* __restrict__ dtb)
{
    int idx = blockIdx.x * blockDim.x + threadIdx.x;
    if (idx >= NROWS * NH) return;
    int h = idx & 7;
    int r = idx >> 3;
    float v = g_zxbcdt[(size_t)r * DPROJ + (DPROJ - NH) + h] + dtb[h];
    g_dtsp[idx] = (v > 20.f) ? v : log1pf(__expf(v));
}

/* per-chunk cumsum of dA = dt * A  -> g_acs ; chunk decay -> g_cdec   */
__global__ void acs_kernel(const float* __restrict__ A_log)
{
    __shared__ float sh[64];
    int id = blockIdx.x;                 /* (b*NH+h)*NC + c */
    int c  = id % NC;
    int bh = id / NC;
    int h  = bh % NH;
    int b  = bh / NH;
    int l  = threadIdx.x;
    float Ah = -expf(A_log[h]);
    sh[l] = g_dtsp[(size_t)(b * L_SZ + c * 64 + l) * NH + h] * Ah;
    __syncthreads();
    for (int off = 1; off < 64; off <<= 1) {
        float v = (l >= off) ? sh[l - off] : 0.f;
        __syncthreads();
        sh[l] += v;
        __syncthreads();
    }
    g_acs[(size_t)id * 64 + l] = sh[l];
    if (l == 63) g_cdec[id] = __expf(sh[63]);
}

/* ------------------------------------------------------------------ */
/* Chunk kernel: per (b,c): G = C·B^T once, then per head:             */
/*   Y_diag + Dp*X  -> g_y ;  chunk states -> g_states                 */
/* dyn smem: sC/sB/sX/sG 64x65 each + sAcs + sDec  = 67072 B           */
/* ------------------------------------------------------------------ */
extern __shared__ float smem[];
__global__ void chunk_kernel(const float* __restrict__ Dp)
{
    float* sC   = smem;                 /* also reused as sM */
    float* sB   = smem + 4160;
    float* sX   = smem + 8320;
    float* sG   = smem + 12480;
    float* sM   = sC;
    float* sAcs = smem + 16640;
    float* sDec = smem + 16704;

    int bc = blockIdx.x;
    int b = bc / NC, c = bc % NC;
    int tid = threadIdx.x;
    int base = b * L_SZ + c * CHUNK;

    for (int i = tid; i < 64 * 64; i += 256) {
        int l = i >> 6, n = i & 63;
        const float* row = g_xbc + (size_t)(base + l) * CONVD;
        sB[l * 65 + n] = row[DINNER + n];
        sC[l * 65 + n] = row[DINNER + DSTATE + n];
    }
    __syncthreads();
    for (int i = tid; i < 64 * 64; i += 256) {
        int l = i >> 6, s = i & 63;
        float acc = 0.f;
#pragma unroll 8
        for (int n = 0; n < 64; n++) acc += sC[l * 65 + n] * sB[s * 65 + n];
        sG[l * 65 + s] = acc;
    }
    __syncthreads();

    for (int h = 0; h < NH; h++) {
        for (int i = tid; i < 64 * 64; i += 256) {
            int s = i >> 6, p = i & 63;
            int r = base + s;
            sX[s * 65 + p] = g_xbc[(size_t)r * CONVD + h * HD + p]
                           * g_dtsp[(size_t)r * NH + h];
        }
        if (tid < 64) sAcs[tid] = g_acs[((size_t)(b * NH + h) * NC + c) * 64 + tid];
        __syncthreads();
        for (int i = tid; i < 64 * 64; i += 256) {
            int l = i >> 6, s = i & 63;
            sM[l * 65 + s] = (s <= l) ? sG[l * 65 + s] * __expf(sAcs[l] - sAcs[s]) : 0.f;
        }
        if (tid < 64) sDec[tid] = __expf(sAcs[63] - sAcs[tid]);
        __syncthreads();
        float Dph = Dp[h];
        for (int i = tid; i < 64 * 64; i += 256) {
            int l = i >> 6, p = i & 63;
            float acc = 0.f;
#pragma unroll 8
            for (int s = 0; s < 64; s++) acc += sM[l * 65 + s] * sX[s * 65 + p];
            int r = base + l;
            g_y[(size_t)r * DINNER + h * HD + p] =
                acc + Dph * g_xbc[(size_t)r * CONVD + h * HD + p];
        }
        for (int i = tid; i < 64 * 64; i += 256) {
            int p = i >> 6, n = i & 63;
            float acc = 0.f;
#pragma unroll 8
            for (int l = 0; l < 64; l++)
                acc += sB[l * 65 + n] * sDec[l] * sX[l * 65 + p];
            g_states[((((size_t)(b * NC + c) * NH + h) * HD + p) << 6) + n] = acc;
        }
        __syncthreads();
    }
}

/* sequential inter-chunk state recurrence (32 steps)                  */
__global__ void scan_kernel(void)
{
    int idx = blockIdx.x * blockDim.x + threadIdx.x;  /* < 1048576 */
    int n = idx & 63;
    int p = (idx >> 6) & 63;
    int h = (idx >> 12) & 7;
    int b = idx >> 15;
    float carry = 0.f;
    for (int c = 0; c < NC; c++) {
        size_t off = (((size_t)(b * NC + c) * NH + h) << 12) + (p << 6) + n;
        g_prev[off] = carry;
        carry = carry * g_cdec[(b * NH + h) * NC + c] + g_states[off];
    }
}

/* Y_off: per (b,c,h): exp(Acs[l]) * (C @ prev^T) added into g_y       */
__global__ void yoff_kernel(void)
{
    __shared__ float sC[64 * 65];
    __shared__ float sP[64 * 65];
    __shared__ float sE[64];
    int id = blockIdx.x;                 /* b*NC*NH + c*NH + h */
    int h = id % NH;
    int c = (id / NH) % NC;
    int b = id / (NH * NC);
    int tid = threadIdx.x;
    int base = b * L_SZ + c * CHUNK;
    for (int i = tid; i < 4096; i += 256) {
        int l = i >> 6, n = i & 63;
        sC[l * 65 + n] = g_xbc[(size_t)(base + l) * CONVD + DINNER + DSTATE + n];
        sP[l * 65 + n] = g_prev[(((size_t)(b * NC + c) * NH + h) << 12) + i];
    }
    if (tid < 64) sE[tid] = __expf(g_acs[((size_t)(b * NH + h) * NC + c) * 64 + tid]);
    __syncthreads();
    for (int i = tid; i < 4096; i += 256) {
        int l = i >> 6, p = i & 63;
        float acc = 0.f;
#pragma unroll 8
        for (int n = 0; n < 64; n++) acc += sC[l * 65 + n] * sP[p * 65 + n];
        size_t o = (size_t)(base + l) * DINNER + h * HD + p;
        g_y[o] += acc * sE[l];
    }
}

/* u = y*silu(z); RMSNorm(u)*norm_w -> g_yn                            */
__global__ void gate_rms(const float* __restrict__ nw)
{
    __shared__ float red[256];
    int r = blockIdx.x, tid = threadIdx.x;
    const float* zrow = g_zxbcdt + (size_t)r * DPROJ;
    const float* yrow = g_y + (size_t)r * DINNER;
    float z0 = zrow[tid], z1 = zrow[tid + 256];
    float u0 = yrow[tid]       * (z0 / (1.f + __expf(-z0)));
    float u1 = yrow[tid + 256] * (z1 / (1.f + __expf(-z1)));
    red[tid] = u0 * u0 + u1 * u1;
    __syncthreads();
    for (int s = 128; s > 0; s >>= 1) {
        if (tid < s) red[tid] += red[tid + s];
        __syncthreads();
    }
    float scale = rsqrtf(red[0] / 512.f + 1e-12f);
    g_yn[(size_t)r * DINNER + tid]       = u0 * scale * nw[tid];
    g_yn[(size_t)r * DINNER + tid + 256] = u1 * scale * nw[tid + 256];
}

/* LayerNorm(a + res) * g + b                                          */
__global__ void ln_res(const float* __restrict__ a, const float* __restrict__ res,
                       const float* __restrict__ g, const float* __restrict__ bb,
                       float* __restrict__ out)
{
    __shared__ float red[256];
    int r = blockIdx.x, tid = threadIdx.x;
    float x = a[(size_t)r * 256 + tid] + res[(size_t)r * 256 + tid];
    red[tid] = x;
    __syncthreads();
    for (int s = 128; s > 0; s >>= 1) {
        if (tid < s) red[tid] += red[tid + s];
        __syncthreads();
    }
    float mean = red[0] / 256.f;
    __syncthreads();
    float d = x - mean;
    red[tid] = d * d;
    __syncthreads();
    for (int s = 128; s > 0; s >>= 1) {
        if (tid < s) red[tid] += red[tid + s];
        __syncthreads();
    }
    float var = red[0] / 256.f;
    out[(size_t)r * 256 + tid] = d * rsqrtf(var + 1e-12f) * g[tid] + bb[tid];
}

/* ------------------------------------------------------------------ */
extern "C" void kernel_launch(void* const* d_in, const int* in_sizes, int n_in,
                              void* d_out, int out_size)
{
    const float* x       = (const float*)d_in[0];
    const float* in_w    = (const float*)d_in[1];
    const float* in_b    = (const float*)d_in[2];
    const float* conv_w  = (const float*)d_in[3];
    const float* conv_b  = (const float*)d_in[4];
    const float* dt_bias = (const float*)d_in[5];
    const float* A_log   = (const float*)d_in[6];
    const float* Dp      = (const float*)d_in[7];
    const float* norm_w  = (const float*)d_in[8];
    const float* out_w   = (const float*)d_in[9];
    const float* out_b   = (const float*)d_in[10];
    const float* ln_g    = (const float*)d_in[11];
    const float* ln_b    = (const float*)d_in[12];
    const float* fc1_w   = (const float*)d_in[13];
    const float* fc1_b   = (const float*)d_in[14];
    const float* fc2_w   = (const float*)d_in[15];
    const float* fc2_b   = (const float*)d_in[16];
    const float* fln_g   = (const float*)d_in[17];
    const float* fln_b   = (const float*)d_in[18];
    float* out = (float*)d_out;

    void *p;
    cudaGetSymbolAddress(&p, g_zxbcdt);  float* zx     = (float*)p;
    cudaGetSymbolAddress(&p, g_yn);      float* yn     = (float*)p;
    cudaGetSymbolAddress(&p, g_t256);    float* t256   = (float*)p;
    cudaGetSymbolAddress(&p, g_hidden);  float* hidden = (float*)p;
    cudaGetSymbolAddress(&p, g_h1);      float* h1     = (float*)p;

    cudaFuncSetAttribute(chunk_kernel,
                         cudaFuncAttributeMaxDynamicSharedMemorySize, 67072);

    /* 1. in_proj */
    sgemm_bias<<<dim3((DPROJ + 127) / 128, NROWS / 128), 256>>>(
        x, in_w, in_b, zx, NROWS, DPROJ, DMODEL, 0);
    /* 2. conv + silu */
    conv_kernel<<<(NROWS * CONVD + 255) / 256, 256>>>(conv_w, conv_b);
    /* 3. softplus dt */
    dtsp_kernel<<<(NROWS * NH + 255) / 256, 256>>>(dt_bias);
    /* 4. per-chunk cumsum */
    acs_kernel<<<B_SZ * NH * NC, 64>>>(A_log);
    /* 5. intra-chunk Y_diag + states */
    chunk_kernel<<<B_SZ * NC, 256, 67072>>>(Dp);
    /* 6. inter-chunk scan */
    scan_kernel<<<(B_SZ * NH * HD * DSTATE + 255) / 256, 256>>>();
    /* 7. Y_off */
    yoff_kernel<<<B_SZ * NC * NH, 256>>>();
    /* 8. gate + RMSNorm */
    gate_rms<<<NROWS, 256>>>(norm_w);
    /* 9. out_proj */
    sgemm_bias<<<dim3(DMODEL / 128, NROWS / 128), 256>>>(
        yn, out_w, out_b, t256, NROWS, DMODEL, DINNER, 0);
    /* 10. LN(out + x) */
    ln_res<<<NROWS, 256>>>(t256, x, ln_g, ln_b, hidden);
    /* 11. fc1 + hardswish */
    sgemm_bias<<<dim3(DFFN / 128, NROWS / 128), 256>>>(
        hidden, fc1_w, fc1_b, h1, NROWS, DFFN, DMODEL, 1);
    /* 12. fc2 */
    sgemm_bias<<<dim3(DMODEL / 128, NROWS / 128), 256>>>(
        h1, fc2_w, fc2_b, t256, NROWS, DMODEL, DFFN, 0);
    /* 13. final LN */
    ln_res<<<NROWS, 256>>>(t256, hidden, fln_g, fln_b, out);
}

// round 2
// speedup vs baseline: 1.8432x; 1.8432x over previous
#include <cuda_runtime.h>
#include <math.h>
#include <stdint.h>

#define B_SZ    32
#define L_SZ    2048
#define NROWS   (B_SZ*L_SZ)      /* 65536 */
#define DMODEL  256
#define DINNER  512
#define NH      8
#define HD      64
#define DSTATE  64
#define CHUNK   64
#define NC      (L_SZ/CHUNK)     /* 32 */
#define CONVD   640
#define DPROJ   1160
#define DFFN    1024

/* ------------------------------------------------------------------ */
/* Scratch (device globals; no allocation allowed)                     */
/* ------------------------------------------------------------------ */
__device__ float g_zxbcdt[(size_t)NROWS*DPROJ];
__device__ float g_xbc[(size_t)NROWS*CONVD];
__device__ float g_dtsp[(size_t)NROWS*NH];
__device__ float g_acs[(size_t)B_SZ*NH*L_SZ];
__device__ float g_cdec[B_SZ*NH*NC];
__device__ float g_states[(size_t)B_SZ*NC*NH*HD*DSTATE];
__device__ float g_prev[(size_t)B_SZ*NC*NH*HD*DSTATE];
__device__ float g_y[(size_t)NROWS*DINNER];
__device__ float g_yn[(size_t)NROWS*DINNER];
__device__ float g_t256[(size_t)NROWS*DMODEL];
__device__ float g_hidden[(size_t)NROWS*DMODEL];
__device__ float g_h1[(size_t)NROWS*DFFN];

/* ------------------------------------------------------------------ */
/* tf32 tensor-core GEMM: C[M,N] = A[M,K] @ W[N,K]^T + bias (+act)     */
/* BM=BN=128, BK=32, 256 threads = 8 warps (4m x 2n).                  */
/* Each warp: 32x64 tile = 2 m16 x 8 n8 mma tiles.                     */
/* A row-major [M,K]; W row-major [N,K] == col-major B operand.        */
/* M % 128 == 0, K % 32 == 0; N bounds-checked.                        */
/* ------------------------------------------------------------------ */
#define SROW 36          /* smem row stride in floats (pad, 16B-aligned) */
#define TBUF (128*SROW)  /* floats per tile buffer = 4608 */

__device__ __forceinline__ uint32_t f2tf32(float v) {
    uint32_t r;
    asm("cvt.rna.tf32.f32 %0, %1;" : "=r"(r) : "f"(v));
    return r;
}

__device__ __forceinline__ void mma_tf32(float c[4],
    uint32_t a0, uint32_t a1, uint32_t a2, uint32_t a3,
    uint32_t b0, uint32_t b1)
{
    asm volatile(
        "mma.sync.aligned.m16n8k8.row.col.f32.tf32.tf32.f32 "
        "{%0,%1,%2,%3}, {%4,%5,%6,%7}, {%8,%9}, {%0,%1,%2,%3};"
        : "+f"(c[0]), "+f"(c[1]), "+f"(c[2]), "+f"(c[3])
        : "r"(a0), "r"(a1), "r"(a2), "r"(a3), "r"(b0), "r"(b1));
}

__device__ __forceinline__ void cpa16(uint32_t sdst, const float* gsrc) {
    asm volatile("cp.async.cg.shared.global [%0], [%1], 16;"
                 :: "r"(sdst), "l"(gsrc));
}
__device__ __forceinline__ void cpa16z(uint32_t sdst, const float* gsrc, int valid) {
    int sz = valid ? 16 : 0;
    asm volatile("cp.async.cg.shared.global [%0], [%1], 16, %2;"
                 :: "r"(sdst), "l"(gsrc), "r"(sz));
}

__global__ void __launch_bounds__(256, 2)
gemm_tf32(const float* __restrict__ A, const float* __restrict__ W,
          const float* __restrict__ bias, float* __restrict__ C,
          int M, int N, int K, int act)
{
    extern __shared__ float sm[];
    float* As = sm;              /* 2 buffers x TBUF */
    float* Ws = sm + 2 * TBUF;
    uint32_t sAs = (uint32_t)__cvta_generic_to_shared(As);
    uint32_t sWs = (uint32_t)__cvta_generic_to_shared(Ws);

    int tid  = threadIdx.x;
    int warp = tid >> 5, lane = tid & 31;
    int wm = (warp >> 1) * 32;
    int wn = (warp & 1) * 64;
    int m0 = blockIdx.y * 128;
    int n0 = blockIdx.x * 128;
    int g  = lane >> 2;          /* groupID 0..7 */
    int tg = lane & 3;           /* thread-in-group */

    float acc[2][8][4];
#pragma unroll
    for (int i = 0; i < 2; i++)
#pragma unroll
        for (int j = 0; j < 8; j++)
#pragma unroll
            for (int r = 0; r < 4; r++) acc[i][j][r] = 0.f;

    /* fill chunk mapping: 1024 chunks of 16B per tile; 4 per thread */
    int c0r[4], c0c[4];
#pragma unroll
    for (int i = 0; i < 4; i++) {
        int c = tid + i * 256;
        c0r[i] = c >> 3;
        c0c[i] = (c & 7) * 4;
    }

    int ntiles = K >> 5;

#define FILL(BUF, K0) do {                                                   \
    int _k0 = (K0);                                                          \
    _Pragma("unroll")                                                        \
    for (int i = 0; i < 4; i++) {                                            \
        int row = c0r[i], cc = c0c[i];                                       \
        cpa16(sAs + (((BUF)*TBUF + row*SROW + cc) << 2),                     \
              A + (size_t)(m0 + row) * K + _k0 + cc);                        \
        int wr = n0 + row;                                                   \
        int wv = wr < N;                                                     \
        cpa16z(sWs + (((BUF)*TBUF + row*SROW + cc) << 2),                    \
               W + (size_t)(wv ? wr : 0) * K + _k0 + cc, wv);                \
    }                                                                        \
    asm volatile("cp.async.commit_group;");                                  \
} while (0)

    FILL(0, 0);
    int buf = 0;
    for (int kt = 0; kt < ntiles; kt++) {
        if (kt + 1 < ntiles) {
            FILL(buf ^ 1, (kt + 1) * 32);
            asm volatile("cp.async.wait_group 1;");
        } else {
            asm volatile("cp.async.wait_group 0;");
        }
        __syncthreads();

        const float* Ab = As + buf * TBUF;
        const float* Wb = Ws + buf * TBUF;
#pragma unroll
        for (int ks = 0; ks < 4; ks++) {
            int k0 = ks * 8;
            uint32_t af[2][4];
#pragma unroll
            for (int mt = 0; mt < 2; mt++) {
                const float* ap = Ab + (wm + mt * 16 + g) * SROW + k0 + tg;
                af[mt][0] = f2tf32(ap[0]);
                af[mt][1] = f2tf32(ap[8 * SROW]);
                af[mt][2] = f2tf32(ap[4]);
                af[mt][3] = f2tf32(ap[8 * SROW + 4]);
            }
            uint32_t bf[8][2];
#pragma unroll
            for (int nt = 0; nt < 8; nt++) {
                const float* bp = Wb + (wn + nt * 8 + g) * SROW + k0 + tg;
                bf[nt][0] = f2tf32(bp[0]);
                bf[nt][1] = f2tf32(bp[4]);
            }
#pragma unroll
            for (int mt = 0; mt < 2; mt++)
#pragma unroll
                for (int nt = 0; nt < 8; nt++)
                    mma_tf32(acc[mt][nt], af[mt][0], af[mt][1], af[mt][2],
                             af[mt][3], bf[nt][0], bf[nt][1]);
        }
        __syncthreads();
        buf ^= 1;
    }

    /* epilogue */
#pragma unroll
    for (int mt = 0; mt < 2; mt++) {
        int r0 = m0 + wm + mt * 16 + g;
#pragma unroll
        for (int nt = 0; nt < 8; nt++) {
            int col = n0 + wn + nt * 8 + 2 * tg;
            if (col + 1 < N) {
                float b0 = bias[col], b1 = bias[col + 1];
                float v0 = acc[mt][nt][0] + b0;
                float v1 = acc[mt][nt][1] + b1;
                float v2 = acc[mt][nt][2] + b0;
                float v3 = acc[mt][nt][3] + b1;
                if (act == 1) {
                    float t;
                    t = fminf(fmaxf(v0 + 3.f, 0.f), 6.f); v0 = v0 * t * (1.f/6.f);
                    t = fminf(fmaxf(v1 + 3.f, 0.f), 6.f); v1 = v1 * t * (1.f/6.f);
                    t = fminf(fmaxf(v2 + 3.f, 0.f), 6.f); v2 = v2 * t * (1.f/6.f);
                    t = fminf(fmaxf(v3 + 3.f, 0.f), 6.f); v3 = v3 * t * (1.f/6.f);
                }
                *(float2*)(C + (size_t)r0 * N + col)       = make_float2(v0, v1);
                *(float2*)(C + (size_t)(r0 + 8) * N + col) = make_float2(v2, v3);
            } else if (col < N) {
                float b0 = bias[col];
                float v0 = acc[mt][nt][0] + b0;
                float v2 = acc[mt][nt][2] + b0;
                if (act == 1) {
                    float t;
                    t = fminf(fmaxf(v0 + 3.f, 0.f), 6.f); v0 = v0 * t * (1.f/6.f);
                    t = fminf(fmaxf(v2 + 3.f, 0.f), 6.f); v2 = v2 * t * (1.f/6.f);
                }
                C[(size_t)r0 * N + col]       = v0;
                C[(size_t)(r0 + 8) * N + col] = v2;
            }
        }
    }
}

/* ------------------------------------------------------------------ */
/* Causal conv (K=4) + SiLU over the xBC slice of zxbcdt               */
/* ------------------------------------------------------------------ */
__global__ void conv_kernel(const float* __restrict__ w, const float* __restrict__ cb)
{
    int idx = blockIdx.x * blockDim.x + threadIdx.x;
    if (idx >= NROWS * CONVD) return;
    int ch = idx % CONVD;
    int r  = idx / CONVD;
    int l  = r % L_SZ;
    int b  = r / L_SZ;
    float acc = cb[ch];
#pragma unroll
    for (int k = 0; k < 4; k++) {
        int ls = l + k - 3;
        if (ls >= 0)
            acc += g_zxbcdt[(size_t)(b * L_SZ + ls) * DPROJ + DINNER + ch] * w[ch * 4 + k];
    }
    acc = acc / (1.f + __expf(-acc));
    g_xbc[idx] = acc;
}

/* softplus(dt + dt_bias) */
__global__ void dtsp_kernel(const float* __restrict__ dtb)
{
    int idx = blockIdx.x * blockDim.x + threadIdx.x;
    if (idx >= NROWS * NH) return;
    int h = idx & 7;
    int r = idx >> 3;
    float v = g_zxbcdt[(size_t)r * DPROJ + (DPROJ - NH) + h] + dtb[h];
    g_dtsp[idx] = (v > 20.f) ? v : log1pf(__expf(v));
}

/* per-chunk cumsum of dA = dt * A  -> g_acs ; chunk decay -> g_cdec   */
__global__ void acs_kernel(const float* __restrict__ A_log)
{
    __shared__ float sh[64];
    int id = blockIdx.x;
    int c  = id % NC;
    int bh = id / NC;
    int h  = bh % NH;
    int b  = bh / NH;
    int l  = threadIdx.x;
    float Ah = -expf(A_log[h]);
    sh[l] = g_dtsp[(size_t)(b * L_SZ + c * 64 + l) * NH + h] * Ah;
    __syncthreads();
    for (int off = 1; off < 64; off <<= 1) {
        float v = (l >= off) ? sh[l - off] : 0.f;
        __syncthreads();
        sh[l] += v;
        __syncthreads();
    }
    g_acs[(size_t)id * 64 + l] = sh[l];
    if (l == 63) g_cdec[id] = __expf(sh[63]);
}

/* ------------------------------------------------------------------ */
/* Chunk kernel: per (b,c): G = C·B^T once, then per head              */
/* ------------------------------------------------------------------ */
extern __shared__ float smem[];
__global__ void chunk_kernel(const float* __restrict__ Dp)
{
    float* sC   = smem;
    float* sB   = smem + 4160;
    float* sX   = smem + 8320;
    float* sG   = smem + 12480;
    float* sM   = sC;
    float* sAcs = smem + 16640;
    float* sDec = smem + 16704;

    int bc = blockIdx.x;
    int b = bc / NC, c = bc % NC;
    int tid = threadIdx.x;
    int base = b * L_SZ + c * CHUNK;

    for (int i = tid; i < 64 * 64; i += 256) {
        int l = i >> 6, n = i & 63;
        const float* row = g_xbc + (size_t)(base + l) * CONVD;
        sB[l * 65 + n] = row[DINNER + n];
        sC[l * 65 + n] = row[DINNER + DSTATE + n];
    }
    __syncthreads();
    for (int i = tid; i < 64 * 64; i += 256) {
        int l = i >> 6, s = i & 63;
        float acc = 0.f;
#pragma unroll 8
        for (int n = 0; n < 64; n++) acc += sC[l * 65 + n] * sB[s * 65 + n];
        sG[l * 65 + s] = acc;
    }
    __syncthreads();

    for (int h = 0; h < NH; h++) {
        for (int i = tid; i < 64 * 64; i += 256) {
            int s = i >> 6, p = i & 63;
            int r = base + s;
            sX[s * 65 + p] = g_xbc[(size_t)r * CONVD + h * HD + p]
                           * g_dtsp[(size_t)r * NH + h];
        }
        if (tid < 64) sAcs[tid] = g_acs[((size_t)(b * NH + h) * NC + c) * 64 + tid];
        __syncthreads();
        for (int i = tid; i < 64 * 64; i += 256) {
            int l = i >> 6, s = i & 63;
            sM[l * 65 + s] = (s <= l) ? sG[l * 65 + s] * __expf(sAcs[l] - sAcs[s]) : 0.f;
        }
        if (tid < 64) sDec[tid] = __expf(sAcs[63] - sAcs[tid]);
        __syncthreads();
        float Dph = Dp[h];
        for (int i = tid; i < 64 * 64; i += 256) {
            int l = i >> 6, p = i & 63;
            float acc = 0.f;
#pragma unroll 8
            for (int s = 0; s < 64; s++) acc += sM[l * 65 + s] * sX[s * 65 + p];
            int r = base + l;
            g_y[(size_t)r * DINNER + h * HD + p] =
                acc + Dph * g_xbc[(size_t)r * CONVD + h * HD + p];
        }
        for (int i = tid; i < 64 * 64; i += 256) {
            int p = i >> 6, n = i & 63;
            float acc = 0.f;
#pragma unroll 8
            for (int l = 0; l < 64; l++)
                acc += sB[l * 65 + n] * sDec[l] * sX[l * 65 + p];
            g_states[((((size_t)(b * NC + c) * NH + h) * HD + p) << 6) + n] = acc;
        }
        __syncthreads();
    }
}

/* sequential inter-chunk state recurrence (32 steps)                  */
__global__ void scan_kernel(void)
{
    int idx = blockIdx.x * blockDim.x + threadIdx.x;
    int n = idx & 63;
    int p = (idx >> 6) & 63;
    int h = (idx >> 12) & 7;
    int b = idx >> 15;
    float carry = 0.f;
    for (int c = 0; c < NC; c++) {
        size_t off = (((size_t)(b * NC + c) * NH + h) << 12) + (p << 6) + n;
        g_prev[off] = carry;
        carry = carry * g_cdec[(b * NH + h) * NC + c] + g_states[off];
    }
}

/* Y_off: per (b,c,h): exp(Acs[l]) * (C @ prev^T) added into g_y       */
__global__ void yoff_kernel(void)
{
    __shared__ float sC[64 * 65];
    __shared__ float sP[64 * 65];
    __shared__ float sE[64];
    int id = blockIdx.x;
    int h = id % NH;
    int c = (id / NH) % NC;
    int b = id / (NH * NC);
    int tid = threadIdx.x;
    int base = b * L_SZ + c * CHUNK;
    for (int i = tid; i < 4096; i += 256) {
        int l = i >> 6, n = i & 63;
        sC[l * 65 + n] = g_xbc[(size_t)(base + l) * CONVD + DINNER + DSTATE + n];
        sP[l * 65 + n] = g_prev[(((size_t)(b * NC + c) * NH + h) << 12) + i];
    }
    if (tid < 64) sE[tid] = __expf(g_acs[((size_t)(b * NH + h) * NC + c) * 64 + tid]);
    __syncthreads();
    for (int i = tid; i < 4096; i += 256) {
        int l = i >> 6, p = i & 63;
        float acc = 0.f;
#pragma unroll 8
        for (int n = 0; n < 64; n++) acc += sC[l * 65 + n] * sP[p * 65 + n];
        size_t o = (size_t)(base + l) * DINNER + h * HD + p;
        g_y[o] += acc * sE[l];
    }
}

/* u = y*silu(z); RMSNorm(u)*norm_w -> g_yn                            */
__global__ void gate_rms(const float* __restrict__ nw)
{
    __shared__ float red[256];
    int r = blockIdx.x, tid = threadIdx.x;
    const float* zrow = g_zxbcdt + (size_t)r * DPROJ;
    const float* yrow = g_y + (size_t)r * DINNER;
    float z0 = zrow[tid], z1 = zrow[tid + 256];
    float u0 = yrow[tid]       * (z0 / (1.f + __expf(-z0)));
    float u1 = yrow[tid + 256] * (z1 / (1.f + __expf(-z1)));
    red[tid] = u0 * u0 + u1 * u1;
    __syncthreads();
    for (int s = 128; s > 0; s >>= 1) {
        if (tid < s) red[tid] += red[tid + s];
        __syncthreads();
    }
    float scale = rsqrtf(red[0] / 512.f + 1e-12f);
    g_yn[(size_t)r * DINNER + tid]       = u0 * scale * nw[tid];
    g_yn[(size_t)r * DINNER + tid + 256] = u1 * scale * nw[tid + 256];
}

/* LayerNorm(a + res) * g + b                                          */
__global__ void ln_res(const float* __restrict__ a, const float* __restrict__ res,
                       const float* __restrict__ g, const float* __restrict__ bb,
                       float* __restrict__ out)
{
    __shared__ float red[256];
    int r = blockIdx.x, tid = threadIdx.x;
    float x = a[(size_t)r * 256 + tid] + res[(size_t)r * 256 + tid];
    red[tid] = x;
    __syncthreads();
    for (int s = 128; s > 0; s >>= 1) {
        if (tid < s) red[tid] += red[tid + s];
        __syncthreads();
    }
    float mean = red[0] / 256.f;
    __syncthreads();
    float d = x - mean;
    red[tid] = d * d;
    __syncthreads();
    for (int s = 128; s > 0; s >>= 1) {
        if (tid < s) red[tid] += red[tid + s];
        __syncthreads();
    }
    float var = red[0] / 256.f;
    out[(size_t)r * 256 + tid] = d * rsqrtf(var + 1e-12f) * g[tid] + bb[tid];
}

/* ------------------------------------------------------------------ */
extern "C" void kernel_launch(void* const* d_in, const int* in_sizes, int n_in,
                              void* d_out, int out_size)
{
    const float* x       = (const float*)d_in[0];
    const float* in_w    = (const float*)d_in[1];
    const float* in_b    = (const float*)d_in[2];
    const float* conv_w  = (const float*)d_in[3];
    const float* conv_b  = (const float*)d_in[4];
    const float* dt_bias = (const float*)d_in[5];
    const float* A_log   = (const float*)d_in[6];
    const float* Dp      = (const float*)d_in[7];
    const float* norm_w  = (const float*)d_in[8];
    const float* out_w   = (const float*)d_in[9];
    const float* out_b   = (const float*)d_in[10];
    const float* ln_g    = (const float*)d_in[11];
    const float* ln_b    = (const float*)d_in[12];
    const float* fc1_w   = (const float*)d_in[13];
    const float* fc1_b   = (const float*)d_in[14];
    const float* fc2_w   = (const float*)d_in[15];
    const float* fc2_b   = (const float*)d_in[16];
    const float* fln_g   = (const float*)d_in[17];
    const float* fln_b   = (const float*)d_in[18];
    float* out = (float*)d_out;

    void *p;
    cudaGetSymbolAddress(&p, g_zxbcdt);  float* zx     = (float*)p;
    cudaGetSymbolAddress(&p, g_yn);      float* yn     = (float*)p;
    cudaGetSymbolAddress(&p, g_t256);    float* t256   = (float*)p;
    cudaGetSymbolAddress(&p, g_hidden);  float* hidden = (float*)p;
    cudaGetSymbolAddress(&p, g_h1);      float* h1     = (float*)p;

    cudaFuncSetAttribute(chunk_kernel,
                         cudaFuncAttributeMaxDynamicSharedMemorySize, 67072);
    cudaFuncSetAttribute(gemm_tf32,
                         cudaFuncAttributeMaxDynamicSharedMemorySize, 73728);

    /* 1. in_proj */
    gemm_tf32<<<dim3((DPROJ + 127) / 128, NROWS / 128), 256, 73728>>>(
        x, in_w, in_b, zx, NROWS, DPROJ, DMODEL, 0);
    /* 2. conv + silu */
    conv_kernel<<<(NROWS * CONVD + 255) / 256, 256>>>(conv_w, conv_b);
    /* 3. softplus dt */
    dtsp_kernel<<<(NROWS * NH + 255) / 256, 256>>>(dt_bias);
    /* 4. per-chunk cumsum */
    acs_kernel<<<B_SZ * NH * NC, 64>>>(A_log);
    /* 5. intra-chunk Y_diag + states */
    chunk_kernel<<<B_SZ * NC, 256, 67072>>>(Dp);
    /* 6. inter-chunk scan */
    scan_kernel<<<(B_SZ * NH * HD * DSTATE + 255) / 256, 256>>>();
    /* 7. Y_off */
    yoff_kernel<<<B_SZ * NC * NH, 256>>>();
    /* 8. gate + RMSNorm */
    gate_rms<<<NROWS, 256>>>(norm_w);
    /* 9. out_proj */
    gemm_tf32<<<dim3(DMODEL / 128, NROWS / 128), 256, 73728>>>(
        yn, out_w, out_b, t256, NROWS, DMODEL, DINNER, 0);
    /* 10. LN(out + x) */
    ln_res<<<NROWS, 256>>>(t256, x, ln_g, ln_b, hidden);
    /* 11. fc1 + hardswish */
    gemm_tf32<<<dim3(DFFN / 128, NROWS / 128), 256, 73728>>>(
        hidden, fc1_w, fc1_b, h1, NROWS, DFFN, DMODEL, 1);
    /* 12. fc2 */
    gemm_tf32<<<dim3(DMODEL / 128, NROWS / 128), 256, 73728>>>(
        h1, fc2_w, fc2_b, t256, NROWS, DMODEL, DFFN, 0);
    /* 13. final LN */
    ln_res<<<NROWS, 256>>>(t256, hidden, fln_g, fln_b, out);
}

// round 3
// speedup vs baseline: 1.8580x; 1.0080x over previous
#include <cuda_runtime.h>
#include <math.h>
#include <stdint.h>

#define B_SZ    32
#define L_SZ    2048
#define NROWS   (B_SZ*L_SZ)      /* 65536 */
#define DMODEL  256
#define DINNER  512
#define NH      8
#define HD      64
#define DSTATE  64
#define CHUNK   64
#define NC      (L_SZ/CHUNK)     /* 32 */
#define CONVD   640
#define DPROJ   1160
#define DFFN    1024

/* ------------------------------------------------------------------ */
/* Scratch (device globals; no allocation allowed)                     */
/* ------------------------------------------------------------------ */
__device__ float g_zxbcdt[(size_t)NROWS*DPROJ];
__device__ float g_xbc[(size_t)NROWS*CONVD];
__device__ float g_dtsp[(size_t)NROWS*NH];
__device__ float g_acs[(size_t)B_SZ*NH*L_SZ];
__device__ float g_cdec[B_SZ*NH*NC];
__device__ float g_states[(size_t)B_SZ*NC*NH*HD*DSTATE];
__device__ float g_prev[(size_t)B_SZ*NC*NH*HD*DSTATE];
__device__ float g_y[(size_t)NROWS*DINNER];
__device__ float g_yn[(size_t)NROWS*DINNER];     /* tf32-rounded */
__device__ float g_t256[(size_t)NROWS*DMODEL];
__device__ float g_hidden[(size_t)NROWS*DMODEL]; /* tf32-rounded */
__device__ float g_h1[(size_t)NROWS*DFFN];       /* tf32-rounded */
__device__ float g_xtf[(size_t)NROWS*DMODEL];    /* tf32 copy of x */

/* tf32 copies of weights, packed into one buffer */
#define W_IN_OFF   0
#define W_OUT_OFF  (DPROJ*DMODEL)                          /* 296960 */
#define W_FC1_OFF  (W_OUT_OFF + DMODEL*DINNER)             /* +131072 */
#define W_FC2_OFF  (W_FC1_OFF + DFFN*DMODEL)               /* +262144 */
#define W_TOTAL    (W_FC2_OFF + DMODEL*DFFN)
__device__ float g_wtf[W_TOTAL];

__device__ __forceinline__ uint32_t f2tf32(float v) {
    uint32_t r;
    asm("cvt.rna.tf32.f32 %0, %1;" : "=r"(r) : "f"(v));
    return r;
}
__device__ __forceinline__ float tf32r(float v) {
    return __uint_as_float(f2tf32(v));
}

__global__ void cvt_tf32(const float* __restrict__ src, float* __restrict__ dst, int n)
{
    int i = blockIdx.x * blockDim.x + threadIdx.x;
    if (i < n) dst[i] = tf32r(src[i]);
}

/* ------------------------------------------------------------------ */
/* tf32 tensor-core GEMM: C[M,N] = A[M,K] @ W[N,K]^T + bias (+act)     */
/* A and W must already be tf32-rounded fp32.                          */
/* BM=BN=128, BK=32, 128 threads = 4 warps (2m x 2n), warp = 64x64.    */
/* M % 128 == 0, K % 32 == 0; N bounds-checked.                        */
/* ------------------------------------------------------------------ */
#define SROW 36          /* smem row stride in floats */
#define TBUF (128*SROW)  /* floats per tile buffer = 4608 */

__device__ __forceinline__ void mma_tf32(float c[4],
    uint32_t a0, uint32_t a1, uint32_t a2, uint32_t a3,
    uint32_t b0, uint32_t b1)
{
    asm volatile(
        "mma.sync.aligned.m16n8k8.row.col.f32.tf32.tf32.f32 "
        "{%0,%1,%2,%3}, {%4,%5,%6,%7}, {%8,%9}, {%0,%1,%2,%3};"
        : "+f"(c[0]), "+f"(c[1]), "+f"(c[2]), "+f"(c[3])
        : "r"(a0), "r"(a1), "r"(a2), "r"(a3), "r"(b0), "r"(b1));
}

__device__ __forceinline__ void cpa16(uint32_t sdst, const float* gsrc) {
    asm volatile("cp.async.cg.shared.global [%0], [%1], 16;"
                 :: "r"(sdst), "l"(gsrc));
}
__device__ __forceinline__ void cpa16z(uint32_t sdst, const float* gsrc, int valid) {
    int sz = valid ? 16 : 0;
    asm volatile("cp.async.cg.shared.global [%0], [%1], 16, %2;"
                 :: "r"(sdst), "l"(gsrc), "r"(sz));
}

__global__ void __launch_bounds__(128, 2)
gemm_tf32(const float* __restrict__ A, const float* __restrict__ W,
          const float* __restrict__ bias, float* __restrict__ C,
          int M, int N, int K, int act)
{
    extern __shared__ float sm[];
    float* As = sm;              /* 2 buffers x TBUF */
    float* Ws = sm + 2 * TBUF;
    uint32_t sAs = (uint32_t)__cvta_generic_to_shared(As);
    uint32_t sWs = (uint32_t)__cvta_generic_to_shared(Ws);

    int tid  = threadIdx.x;
    int warp = tid >> 5, lane = tid & 31;
    int wm = (warp >> 1) * 64;
    int wn = (warp & 1) * 64;
    int m0 = blockIdx.y * 128;
    int n0 = blockIdx.x * 128;
    int g  = lane >> 2;          /* 0..7 */
    int tg = lane & 3;           /* 0..3 */

    float acc[4][8][4];
#pragma unroll
    for (int i = 0; i < 4; i++)
#pragma unroll
        for (int j = 0; j < 8; j++)
#pragma unroll
            for (int r = 0; r < 4; r++) acc[i][j][r] = 0.f;

    /* staging: 1024 16B-chunks per tile, 8 per thread */
    int ntiles = K >> 5;

#define FILL(BUF, K0) do {                                                   \
    int _k0 = (K0);                                                          \
    _Pragma("unroll")                                                        \
    for (int i = 0; i < 8; i++) {                                            \
        int c = tid + i * 128;                                               \
        int row = c >> 3, cc = (c & 7) * 4;                                  \
        cpa16(sAs + (((BUF)*TBUF + row*SROW + cc) << 2),                     \
              A + (size_t)(m0 + row) * K + _k0 + cc);                        \
        int wr = n0 + row;                                                   \
        int wv = wr < N;                                                     \
        cpa16z(sWs + (((BUF)*TBUF + row*SROW + cc) << 2),                    \
               W + (size_t)(wv ? wr : 0) * K + _k0 + cc, wv);                \
    }                                                                        \
    asm volatile("cp.async.commit_group;");                                  \
} while (0)

    FILL(0, 0);
    int buf = 0;
    for (int kt = 0; kt < ntiles; kt++) {
        if (kt + 1 < ntiles) {
            FILL(buf ^ 1, (kt + 1) * 32);
            asm volatile("cp.async.wait_group 1;");
        } else {
            asm volatile("cp.async.wait_group 0;");
        }
        __syncthreads();

        const uint32_t* Ab = (const uint32_t*)(As + buf * TBUF);
        const uint32_t* Wb = (const uint32_t*)(Ws + buf * TBUF);
#pragma unroll
        for (int ks = 0; ks < 4; ks++) {
            int k0 = ks * 8;
            uint32_t af[4][4];
#pragma unroll
            for (int mt = 0; mt < 4; mt++) {
                const uint32_t* ap = Ab + (wm + mt * 16 + g) * SROW + k0 + tg;
                af[mt][0] = ap[0];
                af[mt][1] = ap[8 * SROW];
                af[mt][2] = ap[4];
                af[mt][3] = ap[8 * SROW + 4];
            }
            uint32_t bf[8][2];
#pragma unroll
            for (int nt = 0; nt < 8; nt++) {
                const uint32_t* bp = Wb + (wn + nt * 8 + g) * SROW + k0 + tg;
                bf[nt][0] = bp[0];
                bf[nt][1] = bp[4];
            }
#pragma unroll
            for (int mt = 0; mt < 4; mt++)
#pragma unroll
                for (int nt = 0; nt < 8; nt++)
                    mma_tf32(acc[mt][nt], af[mt][0], af[mt][1], af[mt][2],
                             af[mt][3], bf[nt][0], bf[nt][1]);
        }
        __syncthreads();
        buf ^= 1;
    }

    /* epilogue: act 0 = none, 1 = hardswish + tf32 round */
#pragma unroll
    for (int mt = 0; mt < 4; mt++) {
        int r0 = m0 + wm + mt * 16 + g;
#pragma unroll
        for (int nt = 0; nt < 8; nt++) {
            int col = n0 + wn + nt * 8 + 2 * tg;
            if (col + 1 < N) {
                float b0 = bias[col], b1 = bias[col + 1];
                float v0 = acc[mt][nt][0] + b0;
                float v1 = acc[mt][nt][1] + b1;
                float v2 = acc[mt][nt][2] + b0;
                float v3 = acc[mt][nt][3] + b1;
                if (act == 1) {
                    float t;
                    t = fminf(fmaxf(v0 + 3.f, 0.f), 6.f); v0 = tf32r(v0 * t * (1.f/6.f));
                    t = fminf(fmaxf(v1 + 3.f, 0.f), 6.f); v1 = tf32r(v1 * t * (1.f/6.f));
                    t = fminf(fmaxf(v2 + 3.f, 0.f), 6.f); v2 = tf32r(v2 * t * (1.f/6.f));
                    t = fminf(fmaxf(v3 + 3.f, 0.f), 6.f); v3 = tf32r(v3 * t * (1.f/6.f));
                }
                *(float2*)(C + (size_t)r0 * N + col)       = make_float2(v0, v1);
                *(float2*)(C + (size_t)(r0 + 8) * N + col) = make_float2(v2, v3);
            } else if (col < N) {
                float b0 = bias[col];
                float v0 = acc[mt][nt][0] + b0;
                float v2 = acc[mt][nt][2] + b0;
                if (act == 1) {
                    float t;
                    t = fminf(fmaxf(v0 + 3.f, 0.f), 6.f); v0 = tf32r(v0 * t * (1.f/6.f));
                    t = fminf(fmaxf(v2 + 3.f, 0.f), 6.f); v2 = tf32r(v2 * t * (1.f/6.f));
                }
                C[(size_t)r0 * N + col]       = v0;
                C[(size_t)(r0 + 8) * N + col] = v2;
            }
        }
    }
}

/* ------------------------------------------------------------------ */
/* Causal conv (K=4) + SiLU over the xBC slice of zxbcdt               */
/* ------------------------------------------------------------------ */
__global__ void conv_kernel(const float* __restrict__ w, const float* __restrict__ cb)
{
    int idx = blockIdx.x * blockDim.x + threadIdx.x;
    if (idx >= NROWS * CONVD) return;
    int ch = idx % CONVD;
    int r  = idx / CONVD;
    int l  = r % L_SZ;
    int b  = r / L_SZ;
    float acc = cb[ch];
#pragma unroll
    for (int k = 0; k < 4; k++) {
        int ls = l + k - 3;
        if (ls >= 0)
            acc += g_zxbcdt[(size_t)(b * L_SZ + ls) * DPROJ + DINNER + ch] * w[ch * 4 + k];
    }
    acc = acc / (1.f + __expf(-acc));
    g_xbc[idx] = acc;
}

/* softplus(dt + dt_bias) */
__global__ void dtsp_kernel(const float* __restrict__ dtb)
{
    int idx = blockIdx.x * blockDim.x + threadIdx.x;
    if (idx >= NROWS * NH) return;
    int h = idx & 7;
    int r = idx >> 3;
    float v = g_zxbcdt[(size_t)r * DPROJ + (DPROJ - NH) + h] + dtb[h];
    g_dtsp[idx] = (v > 20.f) ? v : log1pf(__expf(v));
}

/* per-chunk cumsum of dA = dt * A  -> g_acs ; chunk decay -> g_cdec   */
__global__ void acs_kernel(const float* __restrict__ A_log)
{
    __shared__ float sh[64];
    int id = blockIdx.x;
    int c  = id % NC;
    int bh = id / NC;
    int h  = bh % NH;
    int b  = bh / NH;
    int l  = threadIdx.x;
    float Ah = -expf(A_log[h]);
    sh[l] = g_dtsp[(size_t)(b * L_SZ + c * 64 + l) * NH + h] * Ah;
    __syncthreads();
    for (int off = 1; off < 64; off <<= 1) {
        float v = (l >= off) ? sh[l - off] : 0.f;
        __syncthreads();
        sh[l] += v;
        __syncthreads();
    }
    g_acs[(size_t)id * 64 + l] = sh[l];
    if (l == 63) g_cdec[id] = __expf(sh[63]);
}

/* ------------------------------------------------------------------ */
/* Chunk kernel: per (b,c): G = C·B^T once, then per head              */
/* ------------------------------------------------------------------ */
extern __shared__ float smem[];
__global__ void chunk_kernel(const float* __restrict__ Dp)
{
    float* sC   = smem;
    float* sB   = smem + 4160;
    float* sX   = smem + 8320;
    float* sG   = smem + 12480;
    float* sM   = sC;
    float* sAcs = smem + 16640;
    float* sDec = smem + 16704;

    int bc = blockIdx.x;
    int b = bc / NC, c = bc % NC;
    int tid = threadIdx.x;
    int base = b * L_SZ + c * CHUNK;

    for (int i = tid; i < 64 * 64; i += 256) {
        int l = i >> 6, n = i & 63;
        const float* row = g_xbc + (size_t)(base + l) * CONVD;
        sB[l * 65 + n] = row[DINNER + n];
        sC[l * 65 + n] = row[DINNER + DSTATE + n];
    }
    __syncthreads();
    for (int i = tid; i < 64 * 64; i += 256) {
        int l = i >> 6, s = i & 63;
        float acc = 0.f;
#pragma unroll 8
        for (int n = 0; n < 64; n++) acc += sC[l * 65 + n] * sB[s * 65 + n];
        sG[l * 65 + s] = acc;
    }
    __syncthreads();

    for (int h = 0; h < NH; h++) {
        for (int i = tid; i < 64 * 64; i += 256) {
            int s = i >> 6, p = i & 63;
            int r = base + s;
            sX[s * 65 + p] = g_xbc[(size_t)r * CONVD + h * HD + p]
                           * g_dtsp[(size_t)r * NH + h];
        }
        if (tid < 64) sAcs[tid] = g_acs[((size_t)(b * NH + h) * NC + c) * 64 + tid];
        __syncthreads();
        for (int i = tid; i < 64 * 64; i += 256) {
            int l = i >> 6, s = i & 63;
            sM[l * 65 + s] = (s <= l) ? sG[l * 65 + s] * __expf(sAcs[l] - sAcs[s]) : 0.f;
        }
        if (tid < 64) sDec[tid] = __expf(sAcs[63] - sAcs[tid]);
        __syncthreads();
        float Dph = Dp[h];
        for (int i = tid; i < 64 * 64; i += 256) {
            int l = i >> 6, p = i & 63;
            float acc = 0.f;
#pragma unroll 8
            for (int s = 0; s < 64; s++) acc += sM[l * 65 + s] * sX[s * 65 + p];
            int r = base + l;
            g_y[(size_t)r * DINNER + h * HD + p] =
                acc + Dph * g_xbc[(size_t)r * CONVD + h * HD + p];
        }
        for (int i = tid; i < 64 * 64; i += 256) {
            int p = i >> 6, n = i & 63;
            float acc = 0.f;
#pragma unroll 8
            for (int l = 0; l < 64; l++)
                acc += sB[l * 65 + n] * sDec[l] * sX[l * 65 + p];
            g_states[((((size_t)(b * NC + c) * NH + h) * HD + p) << 6) + n] = acc;
        }
        __syncthreads();
    }
}

/* sequential inter-chunk state recurrence (32 steps)                  */
__global__ void scan_kernel(void)
{
    int idx = blockIdx.x * blockDim.x + threadIdx.x;
    int n = idx & 63;
    int p = (idx >> 6) & 63;
    int h = (idx >> 12) & 7;
    int b = idx >> 15;
    float carry = 0.f;
    for (int c = 0; c < NC; c++) {
        size_t off = (((size_t)(b * NC + c) * NH + h) << 12) + (p << 6) + n;
        g_prev[off] = carry;
        carry = carry * g_cdec[(b * NH + h) * NC + c] + g_states[off];
    }
}

/* Y_off: per (b,c,h): exp(Acs[l]) * (C @ prev^T) added into g_y       */
__global__ void yoff_kernel(void)
{
    __shared__ float sC[64 * 65];
    __shared__ float sP[64 * 65];
    __shared__ float sE[64];
    int id = blockIdx.x;
    int h = id % NH;
    int c = (id / NH) % NC;
    int b = id / (NH * NC);
    int tid = threadIdx.x;
    int base = b * L_SZ + c * CHUNK;
    for (int i = tid; i < 4096; i += 256) {
        int l = i >> 6, n = i & 63;
        sC[l * 65 + n] = g_xbc[(size_t)(base + l) * CONVD + DINNER + DSTATE + n];
        sP[l * 65 + n] = g_prev[(((size_t)(b * NC + c) * NH + h) << 12) + i];
    }
    if (tid < 64) sE[tid] = __expf(g_acs[((size_t)(b * NH + h) * NC + c) * 64 + tid]);
    __syncthreads();
    for (int i = tid; i < 4096; i += 256) {
        int l = i >> 6, p = i & 63;
        float acc = 0.f;
#pragma unroll 8
        for (int n = 0; n < 64; n++) acc += sC[l * 65 + n] * sP[p * 65 + n];
        size_t o = (size_t)(base + l) * DINNER + h * HD + p;
        g_y[o] += acc * sE[l];
    }
}

/* u = y*silu(z); RMSNorm(u)*norm_w -> g_yn (tf32-rounded)             */
__global__ void gate_rms(const float* __restrict__ nw)
{
    __shared__ float red[256];
    int r = blockIdx.x, tid = threadIdx.x;
    const float* zrow = g_zxbcdt + (size_t)r * DPROJ;
    const float* yrow = g_y + (size_t)r * DINNER;
    float z0 = zrow[tid], z1 = zrow[tid + 256];
    float u0 = yrow[tid]       * (z0 / (1.f + __expf(-z0)));
    float u1 = yrow[tid + 256] * (z1 / (1.f + __expf(-z1)));
    red[tid] = u0 * u0 + u1 * u1;
    __syncthreads();
    for (int s = 128; s > 0; s >>= 1) {
        if (tid < s) red[tid] += red[tid + s];
        __syncthreads();
    }
    float scale = rsqrtf(red[0] / 512.f + 1e-12f);
    g_yn[(size_t)r * DINNER + tid]       = tf32r(u0 * scale * nw[tid]);
    g_yn[(size_t)r * DINNER + tid + 256] = tf32r(u1 * scale * nw[tid + 256]);
}

/* LayerNorm(a + res) * g + b  (rnd=1 -> tf32-round output)            */
__global__ void ln_res(const float* __restrict__ a, const float* __restrict__ res,
                       const float* __restrict__ g, const float* __restrict__ bb,
                       float* __restrict__ out, int rnd)
{
    __shared__ float red[256];
    int r = blockIdx.x, tid = threadIdx.x;
    float x = a[(size_t)r * 256 + tid] + res[(size_t)r * 256 + tid];
    red[tid] = x;
    __syncthreads();
    for (int s = 128; s > 0; s >>= 1) {
        if (tid < s) red[tid] += red[tid + s];
        __syncthreads();
    }
    float mean = red[0] / 256.f;
    __syncthreads();
    float d = x - mean;
    red[tid] = d * d;
    __syncthreads();
    for (int s = 128; s > 0; s >>= 1) {
        if (tid < s) red[tid] += red[tid + s];
        __syncthreads();
    }
    float var = red[0] / 256.f;
    float v = d * rsqrtf(var + 1e-12f) * g[tid] + bb[tid];
    out[(size_t)r * 256 + tid] = rnd ? tf32r(v) : v;
}

/* ------------------------------------------------------------------ */
extern "C" void kernel_launch(void* const* d_in, const int* in_sizes, int n_in,
                              void* d_out, int out_size)
{
    const float* x       = (const float*)d_in[0];
    const float* in_w    = (const float*)d_in[1];
    const float* in_b    = (const float*)d_in[2];
    const float* conv_w  = (const float*)d_in[3];
    const float* conv_b  = (const float*)d_in[4];
    const float* dt_bias = (const float*)d_in[5];
    const float* A_log   = (const float*)d_in[6];
    const float* Dp      = (const float*)d_in[7];
    const float* norm_w  = (const float*)d_in[8];
    const float* out_w   = (const float*)d_in[9];
    const float* out_b   = (const float*)d_in[10];
    const float* ln_g    = (const float*)d_in[11];
    const float* ln_b    = (const float*)d_in[12];
    const float* fc1_w   = (const float*)d_in[13];
    const float* fc1_b   = (const float*)d_in[14];
    const float* fc2_w   = (const float*)d_in[15];
    const float* fc2_b   = (const float*)d_in[16];
    const float* fln_g   = (const float*)d_in[17];
    const float* fln_b   = (const float*)d_in[18];
    float* out = (float*)d_out;

    void *p;
    cudaGetSymbolAddress(&p, g_zxbcdt);  float* zx     = (float*)p;
    cudaGetSymbolAddress(&p, g_yn);      float* yn     = (float*)p;
    cudaGetSymbolAddress(&p, g_t256);    float* t256   = (float*)p;
    cudaGetSymbolAddress(&p, g_hidden);  float* hidden = (float*)p;
    cudaGetSymbolAddress(&p, g_h1);      float* h1     = (float*)p;
    cudaGetSymbolAddress(&p, g_xtf);     float* xtf    = (float*)p;
    cudaGetSymbolAddress(&p, g_wtf);     float* wtf    = (float*)p;

    cudaFuncSetAttribute(chunk_kernel,
                         cudaFuncAttributeMaxDynamicSharedMemorySize, 67072);
    cudaFuncSetAttribute(gemm_tf32,
                         cudaFuncAttributeMaxDynamicSharedMemorySize, 73728);

    /* 0. tf32 conversions: x + all 4 weight matrices */
    cvt_tf32<<<(NROWS*DMODEL + 255)/256, 256>>>(x, xtf, NROWS*DMODEL);
    cvt_tf32<<<(DPROJ*DMODEL + 255)/256, 256>>>(in_w,  wtf + W_IN_OFF,  DPROJ*DMODEL);
    cvt_tf32<<<(DMODEL*DINNER + 255)/256, 256>>>(out_w, wtf + W_OUT_OFF, DMODEL*DINNER);
    cvt_tf32<<<(DFFN*DMODEL + 255)/256, 256>>>(fc1_w,  wtf + W_FC1_OFF, DFFN*DMODEL);
    cvt_tf32<<<(DMODEL*DFFN + 255)/256, 256>>>(fc2_w,  wtf + W_FC2_OFF, DMODEL*DFFN);

    /* 1. in_proj */
    gemm_tf32<<<dim3((DPROJ + 127) / 128, NROWS / 128), 128, 73728>>>(
        xtf, wtf + W_IN_OFF, in_b, zx, NROWS, DPROJ, DMODEL, 0);
    /* 2. conv + silu */
    conv_kernel<<<(NROWS * CONVD + 255) / 256, 256>>>(conv_w, conv_b);
    /* 3. softplus dt */
    dtsp_kernel<<<(NROWS * NH + 255) / 256, 256>>>(dt_bias);
    /* 4. per-chunk cumsum */
    acs_kernel<<<B_SZ * NH * NC, 64>>>(A_log);
    /* 5. intra-chunk Y_diag + states */
    chunk_kernel<<<B_SZ * NC, 256, 67072>>>(Dp);
    /* 6. inter-chunk scan */
    scan_kernel<<<(B_SZ * NH * HD * DSTATE + 255) / 256, 256>>>();
    /* 7. Y_off */
    yoff_kernel<<<B_SZ * NC * NH, 256>>>();
    /* 8. gate + RMSNorm (tf32-rounded out) */
    gate_rms<<<NROWS, 256>>>(norm_w);
    /* 9. out_proj */
    gemm_tf32<<<dim3(DMODEL / 128, NROWS / 128), 128, 73728>>>(
        yn, wtf + W_OUT_OFF, out_b, t256, NROWS, DMODEL, DINNER, 0);
    /* 10. LN(out + x) -> hidden (tf32-rounded) */
    ln_res<<<NROWS, 256>>>(t256, x, ln_g, ln_b, hidden, 1);
    /* 11. fc1 + hardswish (tf32-rounded out) */
    gemm_tf32<<<dim3(DFFN / 128, NROWS / 128), 128, 73728>>>(
        hidden, wtf + W_FC1_OFF, fc1_b, h1, NROWS, DFFN, DMODEL, 1);
    /* 12. fc2 */
    gemm_tf32<<<dim3(DMODEL / 128, NROWS / 128), 128, 73728>>>(
        h1, wtf + W_FC2_OFF, fc2_b, t256, NROWS, DMODEL, DFFN, 0);
    /* 13. final LN */
    ln_res<<<NROWS, 256>>>(t256, hidden, fln_g, fln_b, out, 0);
}

// round 4
// speedup vs baseline: 2.8827x; 1.5514x over previous
#include <cuda_runtime.h>
#include <math.h>
#include <stdint.h>

#define B_SZ    32
#define L_SZ    2048
#define NROWS   (B_SZ*L_SZ)      /* 65536 */
#define DMODEL  256
#define DINNER  512
#define NH      8
#define HD      64
#define DSTATE  64
#define CHUNK   64
#define NC      (L_SZ/CHUNK)     /* 32 */
#define CONVD   640
#define DPROJ   1160
#define DFFN    1024

/* ------------------------------------------------------------------ */
__device__ float g_zxbcdt[(size_t)NROWS*DPROJ];
__device__ float g_xbc[(size_t)NROWS*CONVD];
__device__ float g_dtsp[(size_t)NROWS*NH];
__device__ float g_acs[(size_t)B_SZ*NH*L_SZ];
__device__ float g_cdec[B_SZ*NH*NC];
__device__ float g_states[(size_t)B_SZ*NC*NH*HD*DSTATE];
__device__ float g_prev[(size_t)B_SZ*NC*NH*HD*DSTATE];
__device__ float g_y[(size_t)NROWS*DINNER];
__device__ float g_yn[(size_t)NROWS*DINNER];
__device__ float g_t256[(size_t)NROWS*DMODEL];
__device__ float g_hidden[(size_t)NROWS*DMODEL];
__device__ float g_h1[(size_t)NROWS*DFFN];
__device__ float g_xtf[(size_t)NROWS*DMODEL];

#define W_IN_OFF   0
#define W_OUT_OFF  (DPROJ*DMODEL)
#define W_FC1_OFF  (W_OUT_OFF + DMODEL*DINNER)
#define W_FC2_OFF  (W_FC1_OFF + DFFN*DMODEL)
#define W_TOTAL    (W_FC2_OFF + DMODEL*DFFN)
__device__ float g_wtf[W_TOTAL];

__device__ __forceinline__ uint32_t f2tf32(float v) {
    uint32_t r;
    asm("cvt.rna.tf32.f32 %0, %1;" : "=r"(r) : "f"(v));
    return r;
}
__device__ __forceinline__ float tf32r(float v) {
    return __uint_as_float(f2tf32(v));
}

__global__ void cvt_tf32(const float* __restrict__ src, float* __restrict__ dst, int n)
{
    int i = blockIdx.x * blockDim.x + threadIdx.x;
    if (i < n) dst[i] = tf32r(src[i]);
}

/* ------------------------------------------------------------------ */
/* tf32 tensor-core GEMM, 3-stage cp.async pipeline                    */
/* BM=BN=128, BK=32, 128 threads = 4 warps (2m x 2n), warp = 64x64.    */
/* ------------------------------------------------------------------ */
#define SROW 36
#define TBUF (128*SROW)

__device__ __forceinline__ void mma_tf32(float c[4],
    uint32_t a0, uint32_t a1, uint32_t a2, uint32_t a3,
    uint32_t b0, uint32_t b1)
{
    asm volatile(
        "mma.sync.aligned.m16n8k8.row.col.f32.tf32.tf32.f32 "
        "{%0,%1,%2,%3}, {%4,%5,%6,%7}, {%8,%9}, {%0,%1,%2,%3};"
        : "+f"(c[0]), "+f"(c[1]), "+f"(c[2]), "+f"(c[3])
        : "r"(a0), "r"(a1), "r"(a2), "r"(a3), "r"(b0), "r"(b1));
}

__device__ __forceinline__ void cpa16(uint32_t sdst, const float* gsrc) {
    asm volatile("cp.async.cg.shared.global [%0], [%1], 16;"
                 :: "r"(sdst), "l"(gsrc));
}
__device__ __forceinline__ void cpa16z(uint32_t sdst, const float* gsrc, int valid) {
    int sz = valid ? 16 : 0;
    asm volatile("cp.async.cg.shared.global [%0], [%1], 16, %2;"
                 :: "r"(sdst), "l"(gsrc), "r"(sz));
}

__global__ void __launch_bounds__(128, 2)
gemm_tf32(const float* __restrict__ A, const float* __restrict__ W,
          const float* __restrict__ bias, float* __restrict__ C,
          int M, int N, int K, int act)
{
    extern __shared__ float sm[];
    float* As = sm;              /* 3 buffers x TBUF */
    float* Ws = sm + 3 * TBUF;
    uint32_t sAs = (uint32_t)__cvta_generic_to_shared(As);
    uint32_t sWs = (uint32_t)__cvta_generic_to_shared(Ws);

    int tid  = threadIdx.x;
    int warp = tid >> 5, lane = tid & 31;
    int wm = (warp >> 1) * 64;
    int wn = (warp & 1) * 64;
    int m0 = blockIdx.y * 128;
    int n0 = blockIdx.x * 128;
    int g  = lane >> 2;
    int tg = lane & 3;

    float acc[4][8][4];
#pragma unroll
    for (int i = 0; i < 4; i++)
#pragma unroll
        for (int j = 0; j < 8; j++)
#pragma unroll
            for (int r = 0; r < 4; r++) acc[i][j][r] = 0.f;

    int ntiles = K >> 5;

#define FILL(BUF, K0) do {                                                   \
    int _k0 = (K0);                                                          \
    _Pragma("unroll")                                                        \
    for (int i = 0; i < 8; i++) {                                            \
        int c = tid + i * 128;                                               \
        int row = c >> 3, cc = (c & 7) * 4;                                  \
        cpa16(sAs + (((BUF)*TBUF + row*SROW + cc) << 2),                     \
              A + (size_t)(m0 + row) * K + _k0 + cc);                        \
        int wr = n0 + row;                                                   \
        int wv = wr < N;                                                     \
        cpa16z(sWs + (((BUF)*TBUF + row*SROW + cc) << 2),                    \
               W + (size_t)(wv ? wr : 0) * K + _k0 + cc, wv);                \
    }                                                                        \
    asm volatile("cp.async.commit_group;");                                  \
} while (0)

    FILL(0, 0);
    if (ntiles > 1) FILL(1, 32);
    for (int kt = 0; kt < ntiles; kt++) {
        if (kt + 2 < ntiles) {
            FILL((kt + 2) % 3, (kt + 2) * 32);
            asm volatile("cp.async.wait_group 2;");
        } else if (kt + 1 < ntiles) {
            asm volatile("cp.async.wait_group 1;");
        } else {
            asm volatile("cp.async.wait_group 0;");
        }
        __syncthreads();

        int buf = kt % 3;
        const uint32_t* Ab = (const uint32_t*)(As + buf * TBUF);
        const uint32_t* Wb = (const uint32_t*)(Ws + buf * TBUF);
#pragma unroll
        for (int ks = 0; ks < 4; ks++) {
            int k0 = ks * 8;
            uint32_t af[4][4];
#pragma unroll
            for (int mt = 0; mt < 4; mt++) {
                const uint32_t* ap = Ab + (wm + mt * 16 + g) * SROW + k0 + tg;
                af[mt][0] = ap[0];
                af[mt][1] = ap[8 * SROW];
                af[mt][2] = ap[4];
                af[mt][3] = ap[8 * SROW + 4];
            }
            uint32_t bf[8][2];
#pragma unroll
            for (int nt = 0; nt < 8; nt++) {
                const uint32_t* bp = Wb + (wn + nt * 8 + g) * SROW + k0 + tg;
                bf[nt][0] = bp[0];
                bf[nt][1] = bp[4];
            }
#pragma unroll
            for (int mt = 0; mt < 4; mt++)
#pragma unroll
                for (int nt = 0; nt < 8; nt++)
                    mma_tf32(acc[mt][nt], af[mt][0], af[mt][1], af[mt][2],
                             af[mt][3], bf[nt][0], bf[nt][1]);
        }
        __syncthreads();
    }

#pragma unroll
    for (int mt = 0; mt < 4; mt++) {
        int r0 = m0 + wm + mt * 16 + g;
#pragma unroll
        for (int nt = 0; nt < 8; nt++) {
            int col = n0 + wn + nt * 8 + 2 * tg;
            if (col + 1 < N) {
                float b0 = bias[col], b1 = bias[col + 1];
                float v0 = acc[mt][nt][0] + b0;
                float v1 = acc[mt][nt][1] + b1;
                float v2 = acc[mt][nt][2] + b0;
                float v3 = acc[mt][nt][3] + b1;
                if (act == 1) {
                    float t;
                    t = fminf(fmaxf(v0 + 3.f, 0.f), 6.f); v0 = tf32r(v0 * t * (1.f/6.f));
                    t = fminf(fmaxf(v1 + 3.f, 0.f), 6.f); v1 = tf32r(v1 * t * (1.f/6.f));
                    t = fminf(fmaxf(v2 + 3.f, 0.f), 6.f); v2 = tf32r(v2 * t * (1.f/6.f));
                    t = fminf(fmaxf(v3 + 3.f, 0.f), 6.f); v3 = tf32r(v3 * t * (1.f/6.f));
                }
                *(float2*)(C + (size_t)r0 * N + col)       = make_float2(v0, v1);
                *(float2*)(C + (size_t)(r0 + 8) * N + col) = make_float2(v2, v3);
            } else if (col < N) {
                float b0 = bias[col];
                float v0 = acc[mt][nt][0] + b0;
                float v2 = acc[mt][nt][2] + b0;
                if (act == 1) {
                    float t;
                    t = fminf(fmaxf(v0 + 3.f, 0.f), 6.f); v0 = tf32r(v0 * t * (1.f/6.f));
                    t = fminf(fmaxf(v2 + 3.f, 0.f), 6.f); v2 = tf32r(v2 * t * (1.f/6.f));
                }
                C[(size_t)r0 * N + col]       = v0;
                C[(size_t)(r0 + 8) * N + col] = v2;
            }
        }
    }
}

/* ------------------------------------------------------------------ */
__global__ void conv_kernel(const float* __restrict__ w, const float* __restrict__ cb)
{
    int idx = blockIdx.x * blockDim.x + threadIdx.x;
    if (idx >= NROWS * CONVD) return;
    int ch = idx % CONVD;
    int r  = idx / CONVD;
    int l  = r % L_SZ;
    int b  = r / L_SZ;
    float acc = cb[ch];
#pragma unroll
    for (int k = 0; k < 4; k++) {
        int ls = l + k - 3;
        if (ls >= 0)
            acc += g_zxbcdt[(size_t)(b * L_SZ + ls) * DPROJ + DINNER + ch] * w[ch * 4 + k];
    }
    acc = acc / (1.f + __expf(-acc));
    g_xbc[idx] = acc;
}

__global__ void dtsp_kernel(const float* __restrict__ dtb)
{
    int idx = blockIdx.x * blockDim.x + threadIdx.x;
    if (idx >= NROWS * NH) return;
    int h = idx & 7;
    int r = idx >> 3;
    float v = g_zxbcdt[(size_t)r * DPROJ + (DPROJ - NH) + h] + dtb[h];
    g_dtsp[idx] = (v > 20.f) ? v : log1pf(__expf(v));
}

__global__ void acs_kernel(const float* __restrict__ A_log)
{
    __shared__ float sh[64];
    int id = blockIdx.x;
    int c  = id % NC;
    int bh = id / NC;
    int h  = bh % NH;
    int b  = bh / NH;
    int l  = threadIdx.x;
    float Ah = -expf(A_log[h]);
    sh[l] = g_dtsp[(size_t)(b * L_SZ + c * 64 + l) * NH + h] * Ah;
    __syncthreads();
    for (int off = 1; off < 64; off <<= 1) {
        float v = (l >= off) ? sh[l - off] : 0.f;
        __syncthreads();
        sh[l] += v;
        __syncthreads();
    }
    g_acs[(size_t)id * 64 + l] = sh[l];
    if (l == 63) g_cdec[id] = __expf(sh[63]);
}

/* ------------------------------------------------------------------ */
/* Chunk kernel v2: register-blocked 4x4 matmuls                       */
/* smem: sB,sC,sGt,sMt,sX,sXd (64x68 each) + sAcs,sDec,sDt             */
/* ------------------------------------------------------------------ */
#define SR 68
#define SZT (64*SR)   /* 4352 */

extern __shared__ float smem[];
__global__ void __launch_bounds__(256, 2)
chunk_kernel(const float* __restrict__ Dp)
{
    float* sB   = smem;
    float* sC   = smem + SZT;
    float* sGt  = smem + 2*SZT;
    float* sMt  = smem + 3*SZT;
    float* sX   = smem + 4*SZT;
    float* sXd  = smem + 5*SZT;
    float* sAcs = smem + 6*SZT;
    float* sDec = smem + 6*SZT + 64;
    float* sDt  = smem + 6*SZT + 128;

    int bc = blockIdx.x;
    int b = bc / NC, c = bc % NC;
    int tid = threadIdx.x;
    int base = b * L_SZ + c * CHUNK;

    int tr = (tid >> 4) * 4;      /* contiguous 4-row tile */
    int ts = tid & 15;            /* strided row tile: ts+16j */
    int tc = (tid & 15) * 4;      /* contiguous 4-col chunk  */

    /* load B, C (64x64 each) */
    for (int i = tid; i < 1024; i += 256) {
        int l = i >> 4, n4 = (i & 15) * 4;
        const float* row = g_xbc + (size_t)(base + l) * CONVD + DINNER;
        *(float4*)&sB[l * SR + n4] = *(const float4*)(row + n4);
        *(float4*)&sC[l * SR + n4] = *(const float4*)(row + DSTATE + n4);
    }
    __syncthreads();

    /* Gt[s][l] = sum_n C[l][n] * B[s][n]; l=tr..tr+3, s=ts+16j */
    {
        float a[4][4];
#pragma unroll
        for (int i = 0; i < 4; i++)
#pragma unroll
            for (int j = 0; j < 4; j++) a[i][j] = 0.f;
        for (int n = 0; n < 64; n += 4) {
            float4 cv[4], bv[4];
#pragma unroll
            for (int i = 0; i < 4; i++) cv[i] = *(float4*)&sC[(tr + i) * SR + n];
#pragma unroll
            for (int j = 0; j < 4; j++) bv[j] = *(float4*)&sB[(ts + 16 * j) * SR + n];
#pragma unroll
            for (int i = 0; i < 4; i++)
#pragma unroll
                for (int j = 0; j < 4; j++)
                    a[i][j] += cv[i].x * bv[j].x + cv[i].y * bv[j].y
                             + cv[i].z * bv[j].z + cv[i].w * bv[j].w;
        }
#pragma unroll
        for (int i = 0; i < 4; i++)
#pragma unroll
            for (int j = 0; j < 4; j++)
                sGt[(ts + 16 * j) * SR + tr + i] = a[i][j];
    }
    __syncthreads();

    for (int h = 0; h < NH; h++) {
        if (tid < 64) {
            sDt[tid] = g_dtsp[(size_t)(base + tid) * NH + h];
            const float* ac = g_acs + ((size_t)(b * NH + h) * NC + c) * 64;
            float a = ac[tid];
            sAcs[tid] = a;
            sDec[tid] = __expf(ac[63] - a);
        }
        __syncthreads();

        /* X (dt-scaled) and Xd (also chunk-decay scaled) */
        for (int i = tid; i < 1024; i += 256) {
            int s = i >> 4, p4 = (i & 15) * 4;
            float4 xv = *(const float4*)(g_xbc + (size_t)(base + s) * CONVD + h * HD + p4);
            float dts = sDt[s], dec = sDec[s];
            xv.x *= dts; xv.y *= dts; xv.z *= dts; xv.w *= dts;
            *(float4*)&sX[s * SR + p4] = xv;
            xv.x *= dec; xv.y *= dec; xv.z *= dec; xv.w *= dec;
            *(float4*)&sXd[s * SR + p4] = xv;
        }
        /* Mt[s][l] = (s<=l) ? Gt[s][l]*exp(acs[l]-acs[s]) : 0 */
        for (int i = tid; i < 4096; i += 256) {
            int s = i >> 6, l = i & 63;
            sMt[s * SR + l] = (s <= l) ? sGt[s * SR + l] * __expf(sAcs[l] - sAcs[s]) : 0.f;
        }
        __syncthreads();

        /* Y[l][p] = sum_s Mt[s][l]*X[s][p]; outer-product over s */
        {
            float a[4][4];
#pragma unroll
            for (int i = 0; i < 4; i++)
#pragma unroll
                for (int j = 0; j < 4; j++) a[i][j] = 0.f;
            for (int s = 0; s < 64; s++) {
                float4 mv = *(float4*)&sMt[s * SR + tr];
                float4 xv = *(float4*)&sX[s * SR + tc];
                float m[4] = {mv.x, mv.y, mv.z, mv.w};
                float xx[4] = {xv.x, xv.y, xv.z, xv.w};
#pragma unroll
                for (int i = 0; i < 4; i++)
#pragma unroll
                    for (int j = 0; j < 4; j++) a[i][j] += m[i] * xx[j];
            }
            float Dph = Dp[h];
#pragma unroll
            for (int i = 0; i < 4; i++) {
                int r = base + tr + i;
                float4 xr = *(const float4*)(g_xbc + (size_t)r * CONVD + h * HD + tc);
                float4 o;
                o.x = a[i][0] + Dph * xr.x;
                o.y = a[i][1] + Dph * xr.y;
                o.z = a[i][2] + Dph * xr.z;
                o.w = a[i][3] + Dph * xr.w;
                *(float4*)(g_y + (size_t)r * DINNER + h * HD + tc) = o;
            }
        }
        /* states[p][n] = sum_l B[l][n]*Xd[l][p]; outer-product over l */
        {
            float a[4][4];
#pragma unroll
            for (int i = 0; i < 4; i++)
#pragma unroll
                for (int j = 0; j < 4; j++) a[i][j] = 0.f;
            for (int l = 0; l < 64; l++) {
                float4 xv = *(float4*)&sXd[l * SR + tr];   /* p dims */
                float4 bv = *(float4*)&sB[l * SR + tc];    /* n dims */
                float xp[4] = {xv.x, xv.y, xv.z, xv.w};
                float bn[4] = {bv.x, bv.y, bv.z, bv.w};
#pragma unroll
                for (int i = 0; i < 4; i++)
#pragma unroll
                    for (int j = 0; j < 4; j++) a[i][j] += xp[i] * bn[j];
            }
            float* sp = g_states + (((size_t)(b * NC + c) * NH + h) << 12);
#pragma unroll
            for (int i = 0; i < 4; i++)
                *(float4*)(sp + (tr + i) * 64 + tc) =
                    make_float4(a[i][0], a[i][1], a[i][2], a[i][3]);
        }
        __syncthreads();
    }
}

/* sequential inter-chunk state recurrence                              */
__global__ void scan_kernel(void)
{
    int idx = blockIdx.x * blockDim.x + threadIdx.x;
    int n = idx & 63;
    int p = (idx >> 6) & 63;
    int h = (idx >> 12) & 7;
    int b = idx >> 15;
    float carry = 0.f;
    for (int c = 0; c < NC; c++) {
        size_t off = (((size_t)(b * NC + c) * NH + h) << 12) + (p << 6) + n;
        g_prev[off] = carry;
        carry = carry * g_cdec[(b * NH + h) * NC + c] + g_states[off];
    }
}

/* Y_off v2: register-blocked; per (b,c,h) block                        */
__global__ void __launch_bounds__(256, 2)
yoff_kernel(void)
{
    __shared__ float sC[SZT];
    __shared__ float sP[SZT];
    __shared__ float sE[64];
    int id = blockIdx.x;
    int h = id % NH;
    int c = (id / NH) % NC;
    int b = id / (NH * NC);
    int tid = threadIdx.x;
    int base = b * L_SZ + c * CHUNK;
    int tr = (tid >> 4) * 4;
    int ts = tid & 15;

    const float* pv = g_prev + (((size_t)(b * NC + c) * NH + h) << 12);
    for (int i = tid; i < 1024; i += 256) {
        int r = i >> 4, n4 = (i & 15) * 4;
        *(float4*)&sC[r * SR + n4] =
            *(const float4*)(g_xbc + (size_t)(base + r) * CONVD + DINNER + DSTATE + n4);
        *(float4*)&sP[r * SR + n4] = *(const float4*)(pv + r * 64 + n4);
    }
    if (tid < 64) sE[tid] = __expf(g_acs[((size_t)(b * NH + h) * NC + c) * 64 + tid]);
    __syncthreads();

    /* Yoff[l][p] = E[l] * sum_n C[l][n]*P[p][n]; l=tr..+3, p=ts+16j */
    float a[4][4];
#pragma unroll
    for (int i = 0; i < 4; i++)
#pragma unroll
        for (int j = 0; j < 4; j++) a[i][j] = 0.f;
    for (int n = 0; n < 64; n += 4) {
        float4 cv[4], pvv[4];
#pragma unroll
        for (int i = 0; i < 4; i++) cv[i] = *(float4*)&sC[(tr + i) * SR + n];
#pragma unroll
        for (int j = 0; j < 4; j++) pvv[j] = *(float4*)&sP[(ts + 16 * j) * SR + n];
#pragma unroll
        for (int i = 0; i < 4; i++)
#pragma unroll
            for (int j = 0; j < 4; j++)
                a[i][j] += cv[i].x * pvv[j].x + cv[i].y * pvv[j].y
                         + cv[i].z * pvv[j].z + cv[i].w * pvv[j].w;
    }
#pragma unroll
    for (int i = 0; i < 4; i++) {
        int r = base + tr + i;
        float e = sE[tr + i];
#pragma unroll
        for (int j = 0; j < 4; j++) {
            size_t o = (size_t)r * DINNER + h * HD + ts + 16 * j;
            g_y[o] += a[i][j] * e;
        }
    }
}

/* u = y*silu(z); RMSNorm(u)*norm_w -> g_yn (tf32-rounded)             */
__global__ void gate_rms(const float* __restrict__ nw)
{
    __shared__ float red[256];
    int r = blockIdx.x, tid = threadIdx.x;
    const float* zrow = g_zxbcdt + (size_t)r * DPROJ;
    const float* yrow = g_y + (size_t)r * DINNER;
    float z0 = zrow[tid], z1 = zrow[tid + 256];
    float u0 = yrow[tid]       * (z0 / (1.f + __expf(-z0)));
    float u1 = yrow[tid + 256] * (z1 / (1.f + __expf(-z1)));
    red[tid] = u0 * u0 + u1 * u1;
    __syncthreads();
    for (int s = 128; s > 0; s >>= 1) {
        if (tid < s) red[tid] += red[tid + s];
        __syncthreads();
    }
    float scale = rsqrtf(red[0] / 512.f + 1e-12f);
    g_yn[(size_t)r * DINNER + tid]       = tf32r(u0 * scale * nw[tid]);
    g_yn[(size_t)r * DINNER + tid + 256] = tf32r(u1 * scale * nw[tid + 256]);
}

/* LayerNorm(a + res) * g + b                                          */
__global__ void ln_res(const float* __restrict__ a, const float* __restrict__ res,
                       const float* __restrict__ g, const float* __restrict__ bb,
                       float* __restrict__ out, int rnd)
{
    __shared__ float red[256];
    int r = blockIdx.x, tid = threadIdx.x;
    float x = a[(size_t)r * 256 + tid] + res[(size_t)r * 256 + tid];
    red[tid] = x;
    __syncthreads();
    for (int s = 128; s > 0; s >>= 1) {
        if (tid < s) red[tid] += red[tid + s];
        __syncthreads();
    }
    float mean = red[0] / 256.f;
    __syncthreads();
    float d = x - mean;
    red[tid] = d * d;
    __syncthreads();
    for (int s = 128; s > 0; s >>= 1) {
        if (tid < s) red[tid] += red[tid + s];
        __syncthreads();
    }
    float var = red[0] / 256.f;
    float v = d * rsqrtf(var + 1e-12f) * g[tid] + bb[tid];
    out[(size_t)r * 256 + tid] = rnd ? tf32r(v) : v;
}

/* ------------------------------------------------------------------ */
extern "C" void kernel_launch(void* const* d_in, const int* in_sizes, int n_in,
                              void* d_out, int out_size)
{
    const float* x       = (const float*)d_in[0];
    const float* in_w    = (const float*)d_in[1];
    const float* in_b    = (const float*)d_in[2];
    const float* conv_w  = (const float*)d_in[3];
    const float* conv_b  = (const float*)d_in[4];
    const float* dt_bias = (const float*)d_in[5];
    const float* A_log   = (const float*)d_in[6];
    const float* Dp      = (const float*)d_in[7];
    const float* norm_w  = (const float*)d_in[8];
    const float* out_w   = (const float*)d_in[9];
    const float* out_b   = (const float*)d_in[10];
    const float* ln_g    = (const float*)d_in[11];
    const float* ln_b    = (const float*)d_in[12];
    const float* fc1_w   = (const float*)d_in[13];
    const float* fc1_b   = (const float*)d_in[14];
    const float* fc2_w   = (const float*)d_in[15];
    const float* fc2_b   = (const float*)d_in[16];
    const float* fln_g   = (const float*)d_in[17];
    const float* fln_b   = (const float*)d_in[18];
    float* out = (float*)d_out;

    void *p;
    cudaGetSymbolAddress(&p, g_zxbcdt);  float* zx     = (float*)p;
    cudaGetSymbolAddress(&p, g_yn);      float* yn     = (float*)p;
    cudaGetSymbolAddress(&p, g_t256);    float* t256   = (float*)p;
    cudaGetSymbolAddress(&p, g_hidden);  float* hidden = (float*)p;
    cudaGetSymbolAddress(&p, g_h1);      float* h1     = (float*)p;
    cudaGetSymbolAddress(&p, g_xtf);     float* xtf    = (float*)p;
    cudaGetSymbolAddress(&p, g_wtf);     float* wtf    = (float*)p;

    static int chunk_smem = 6 * SZT * 4 + 3 * 64 * 4;   /* 105216 B */
    cudaFuncSetAttribute(chunk_kernel,
                         cudaFuncAttributeMaxDynamicSharedMemorySize, chunk_smem);
    cudaFuncSetAttribute(gemm_tf32,
                         cudaFuncAttributeMaxDynamicSharedMemorySize, 110592);

    /* 0. tf32 conversions */
    cvt_tf32<<<(NROWS*DMODEL + 255)/256, 256>>>(x, xtf, NROWS*DMODEL);
    cvt_tf32<<<(DPROJ*DMODEL + 255)/256, 256>>>(in_w,  wtf + W_IN_OFF,  DPROJ*DMODEL);
    cvt_tf32<<<(DMODEL*DINNER + 255)/256, 256>>>(out_w, wtf + W_OUT_OFF, DMODEL*DINNER);
    cvt_tf32<<<(DFFN*DMODEL + 255)/256, 256>>>(fc1_w,  wtf + W_FC1_OFF, DFFN*DMODEL);
    cvt_tf32<<<(DMODEL*DFFN + 255)/256, 256>>>(fc2_w,  wtf + W_FC2_OFF, DMODEL*DFFN);

    /* 1. in_proj */
    gemm_tf32<<<dim3((DPROJ + 127) / 128, NROWS / 128), 128, 110592>>>(
        xtf, wtf + W_IN_OFF, in_b, zx, NROWS, DPROJ, DMODEL, 0);
    /* 2-4 */
    conv_kernel<<<(NROWS * CONVD + 255) / 256, 256>>>(conv_w, conv_b);
    dtsp_kernel<<<(NROWS * NH + 255) / 256, 256>>>(dt_bias);
    acs_kernel<<<B_SZ * NH * NC, 64>>>(A_log);
    /* 5. intra-chunk */
    chunk_kernel<<<B_SZ * NC, 256, chunk_smem>>>(Dp);
    /* 6. inter-chunk scan */
    scan_kernel<<<(B_SZ * NH * HD * DSTATE + 255) / 256, 256>>>();
    /* 7. Y_off */
    yoff_kernel<<<B_SZ * NC * NH, 256>>>();
    /* 8. gate + RMSNorm */
    gate_rms<<<NROWS, 256>>>(norm_w);
    /* 9. out_proj */
    gemm_tf32<<<dim3(DMODEL / 128, NROWS / 128), 128, 110592>>>(
        yn, wtf + W_OUT_OFF, out_b, t256, NROWS, DMODEL, DINNER, 0);
    /* 10 */
    ln_res<<<NROWS, 256>>>(t256, x, ln_g, ln_b, hidden, 1);
    /* 11 */
    gemm_tf32<<<dim3(DFFN / 128, NROWS / 128), 128, 110592>>>(
        hidden, wtf + W_FC1_OFF, fc1_b, h1, NROWS, DFFN, DMODEL, 1);
    /* 12 */
    gemm_tf32<<<dim3(DMODEL / 128, NROWS / 128), 128, 110592>>>(
        h1, wtf + W_FC2_OFF, fc2_b, t256, NROWS, DMODEL, DFFN, 0);
    /* 13 */
    ln_res<<<NROWS, 256>>>(t256, hidden, fln_g, fln_b, out, 0);
}

// round 6
// speedup vs baseline: 3.0003x; 1.0408x over previous
#include <cuda_runtime.h>
#include <math.h>
#include <stdint.h>

#define B_SZ    32
#define L_SZ    2048
#define NROWS   (B_SZ*L_SZ)      /* 65536 */
#define DMODEL  256
#define DINNER  512
#define NH      8
#define HD      64
#define DSTATE  64
#define CHUNK   64
#define NC      (L_SZ/CHUNK)     /* 32 */
#define CONVD   640
#define DPROJ   1160
#define DFFN    1024

/* ------------------------------------------------------------------ */
__device__ float g_zxbcdt[(size_t)NROWS*DPROJ];
__device__ float g_xbc[(size_t)NROWS*CONVD];
__device__ float g_dtsp[(size_t)NROWS*NH];
__device__ float g_acs[(size_t)B_SZ*NH*L_SZ];
__device__ float g_cdec[B_SZ*NH*NC];
__device__ float g_states[(size_t)B_SZ*NC*NH*HD*DSTATE];  /* [n][p] */
__device__ float g_prev[(size_t)B_SZ*NC*NH*HD*DSTATE];    /* [n][p] */
__device__ float g_y[(size_t)NROWS*DINNER];
__device__ float g_yn[(size_t)NROWS*DINNER];
__device__ float g_t256[(size_t)NROWS*DMODEL];
__device__ float g_hidden[(size_t)NROWS*DMODEL];
__device__ float g_h1[(size_t)NROWS*DFFN];
__device__ float g_xtf[(size_t)NROWS*DMODEL];

#define W_IN_OFF   0
#define W_OUT_OFF  (DPROJ*DMODEL)
#define W_FC1_OFF  (W_OUT_OFF + DMODEL*DINNER)
#define W_FC2_OFF  (W_FC1_OFF + DFFN*DMODEL)
#define W_TOTAL    (W_FC2_OFF + DMODEL*DFFN)
__device__ float g_wtf[W_TOTAL];

__device__ __forceinline__ uint32_t f2tf32(float v) {
    uint32_t r;
    asm("cvt.rna.tf32.f32 %0, %1;" : "=r"(r) : "f"(v));
    return r;
}
__device__ __forceinline__ float tf32r(float v) {
    return __uint_as_float(f2tf32(v));
}

__global__ void cvt_tf32(const float* __restrict__ src, float* __restrict__ dst, int n)
{
    int i = blockIdx.x * blockDim.x + threadIdx.x;
    if (i < n) dst[i] = tf32r(src[i]);
}

/* ------------------------------------------------------------------ */
/* shared mma helper                                                   */
/* ------------------------------------------------------------------ */
__device__ __forceinline__ void mma_tf32(float c[4],
    uint32_t a0, uint32_t a1, uint32_t a2, uint32_t a3,
    uint32_t b0, uint32_t b1)
{
    asm volatile(
        "mma.sync.aligned.m16n8k8.row.col.f32.tf32.tf32.f32 "
        "{%0,%1,%2,%3}, {%4,%5,%6,%7}, {%8,%9}, {%0,%1,%2,%3};"
        : "+f"(c[0]), "+f"(c[1]), "+f"(c[2]), "+f"(c[3])
        : "r"(a0), "r"(a1), "r"(a2), "r"(a3), "r"(b0), "r"(b1));
}

/* ------------------------------------------------------------------ */
/* tf32 tensor-core GEMM, 3-stage cp.async pipeline (R4, proven)       */
/* ------------------------------------------------------------------ */
#define SROW 36
#define TBUF (128*SROW)

__device__ __forceinline__ void cpa16(uint32_t sdst, const float* gsrc) {
    asm volatile("cp.async.cg.shared.global [%0], [%1], 16;"
                 :: "r"(sdst), "l"(gsrc));
}
__device__ __forceinline__ void cpa16z(uint32_t sdst, const float* gsrc, int valid) {
    int sz = valid ? 16 : 0;
    asm volatile("cp.async.cg.shared.global [%0], [%1], 16, %2;"
                 :: "r"(sdst), "l"(gsrc), "r"(sz));
}

__global__ void __launch_bounds__(128, 2)
gemm_tf32(const float* __restrict__ A, const float* __restrict__ W,
          const float* __restrict__ bias, float* __restrict__ C,
          int M, int N, int K, int act)
{
    extern __shared__ float sm[];
    float* As = sm;
    float* Ws = sm + 3 * TBUF;
    uint32_t sAs = (uint32_t)__cvta_generic_to_shared(As);
    uint32_t sWs = (uint32_t)__cvta_generic_to_shared(Ws);

    int tid  = threadIdx.x;
    int warp = tid >> 5, lane = tid & 31;
    int wm = (warp >> 1) * 64;
    int wn = (warp & 1) * 64;
    int m0 = blockIdx.y * 128;
    int n0 = blockIdx.x * 128;
    int g  = lane >> 2;
    int tg = lane & 3;

    float acc[4][8][4];
#pragma unroll
    for (int i = 0; i < 4; i++)
#pragma unroll
        for (int j = 0; j < 8; j++)
#pragma unroll
            for (int r = 0; r < 4; r++) acc[i][j][r] = 0.f;

    int ntiles = K >> 5;

#define FILL(BUF, K0) do {                                                   \
    int _k0 = (K0);                                                          \
    _Pragma("unroll")                                                        \
    for (int i = 0; i < 8; i++) {                                            \
        int c = tid + i * 128;                                               \
        int row = c >> 3, cc = (c & 7) * 4;                                  \
        cpa16(sAs + (((BUF)*TBUF + row*SROW + cc) << 2),                     \
              A + (size_t)(m0 + row) * K + _k0 + cc);                        \
        int wr = n0 + row;                                                   \
        int wv = wr < N;                                                     \
        cpa16z(sWs + (((BUF)*TBUF + row*SROW + cc) << 2),                    \
               W + (size_t)(wv ? wr : 0) * K + _k0 + cc, wv);                \
    }                                                                        \
    asm volatile("cp.async.commit_group;");                                  \
} while (0)

    FILL(0, 0);
    if (ntiles > 1) FILL(1, 32);
    for (int kt = 0; kt < ntiles; kt++) {
        if (kt + 2 < ntiles) {
            FILL((kt + 2) % 3, (kt + 2) * 32);
            asm volatile("cp.async.wait_group 2;");
        } else if (kt + 1 < ntiles) {
            asm volatile("cp.async.wait_group 1;");
        } else {
            asm volatile("cp.async.wait_group 0;");
        }
        __syncthreads();

        int buf = kt % 3;
        const uint32_t* Ab = (const uint32_t*)(As + buf * TBUF);
        const uint32_t* Wb = (const uint32_t*)(Ws + buf * TBUF);
#pragma unroll
        for (int ks = 0; ks < 4; ks++) {
            int k0 = ks * 8;
            uint32_t af[4][4];
#pragma unroll
            for (int mt = 0; mt < 4; mt++) {
                const uint32_t* ap = Ab + (wm + mt * 16 + g) * SROW + k0 + tg;
                af[mt][0] = ap[0];
                af[mt][1] = ap[8 * SROW];
                af[mt][2] = ap[4];
                af[mt][3] = ap[8 * SROW + 4];
            }
            uint32_t bf[8][2];
#pragma unroll
            for (int nt = 0; nt < 8; nt++) {
                const uint32_t* bp = Wb + (wn + nt * 8 + g) * SROW + k0 + tg;
                bf[nt][0] = bp[0];
                bf[nt][1] = bp[4];
            }
#pragma unroll
            for (int mt = 0; mt < 4; mt++)
#pragma unroll
                for (int nt = 0; nt < 8; nt++)
                    mma_tf32(acc[mt][nt], af[mt][0], af[mt][1], af[mt][2],
                             af[mt][3], bf[nt][0], bf[nt][1]);
        }
        __syncthreads();
    }

#pragma unroll
    for (int mt = 0; mt < 4; mt++) {
        int r0 = m0 + wm + mt * 16 + g;
#pragma unroll
        for (int nt = 0; nt < 8; nt++) {
            int col = n0 + wn + nt * 8 + 2 * tg;
            if (col + 1 < N) {
                float b0 = bias[col], b1 = bias[col + 1];
                float v0 = acc[mt][nt][0] + b0;
                float v1 = acc[mt][nt][1] + b1;
                float v2 = acc[mt][nt][2] + b0;
                float v3 = acc[mt][nt][3] + b1;
                if (act == 1) {
                    float t;
                    t = fminf(fmaxf(v0 + 3.f, 0.f), 6.f); v0 = tf32r(v0 * t * (1.f/6.f));
                    t = fminf(fmaxf(v1 + 3.f, 0.f), 6.f); v1 = tf32r(v1 * t * (1.f/6.f));
                    t = fminf(fmaxf(v2 + 3.f, 0.f), 6.f); v2 = tf32r(v2 * t * (1.f/6.f));
                    t = fminf(fmaxf(v3 + 3.f, 0.f), 6.f); v3 = tf32r(v3 * t * (1.f/6.f));
                }
                *(float2*)(C + (size_t)r0 * N + col)       = make_float2(v0, v1);
                *(float2*)(C + (size_t)(r0 + 8) * N + col) = make_float2(v2, v3);
            } else if (col < N) {
                float b0 = bias[col];
                float v0 = acc[mt][nt][0] + b0;
                float v2 = acc[mt][nt][2] + b0;
                if (act == 1) {
                    float t;
                    t = fminf(fmaxf(v0 + 3.f, 0.f), 6.f); v0 = tf32r(v0 * t * (1.f/6.f));
                    t = fminf(fmaxf(v2 + 3.f, 0.f), 6.f); v2 = tf32r(v2 * t * (1.f/6.f));
                }
                C[(size_t)r0 * N + col]       = v0;
                C[(size_t)(r0 + 8) * N + col] = v2;
            }
        }
    }
}

/* ------------------------------------------------------------------ */
/* Causal conv (K=4) + SiLU, float4 vectorized (4 channels/thread)     */
/* ------------------------------------------------------------------ */
__global__ void conv_kernel(const float* __restrict__ w, const float* __restrict__ cb)
{
    int idx = blockIdx.x * blockDim.x + threadIdx.x;
    if (idx >= NROWS * (CONVD / 4)) return;
    int ch4 = (idx % (CONVD / 4)) * 4;
    int r   = idx / (CONVD / 4);
    int l   = r % L_SZ;
    int b   = r / L_SZ;

    float4 w0 = *(const float4*)(w + (ch4 + 0) * 4);
    float4 w1 = *(const float4*)(w + (ch4 + 1) * 4);
    float4 w2 = *(const float4*)(w + (ch4 + 2) * 4);
    float4 w3 = *(const float4*)(w + (ch4 + 3) * 4);
    float wt0[4] = {w0.x, w0.y, w0.z, w0.w};
    float wt1[4] = {w1.x, w1.y, w1.z, w1.w};
    float wt2[4] = {w2.x, w2.y, w2.z, w2.w};
    float wt3[4] = {w3.x, w3.y, w3.z, w3.w};

    float4 acc = *(const float4*)(cb + ch4);
#pragma unroll
    for (int k = 0; k < 4; k++) {
        int ls = l + k - 3;
        if (ls >= 0) {
            float4 xv = *(const float4*)(g_zxbcdt +
                (size_t)(b * L_SZ + ls) * DPROJ + DINNER + ch4);
            acc.x += xv.x * wt0[k];
            acc.y += xv.y * wt1[k];
            acc.z += xv.z * wt2[k];
            acc.w += xv.w * wt3[k];
        }
    }
    acc.x = acc.x / (1.f + __expf(-acc.x));
    acc.y = acc.y / (1.f + __expf(-acc.y));
    acc.z = acc.z / (1.f + __expf(-acc.z));
    acc.w = acc.w / (1.f + __expf(-acc.w));
    *(float4*)(g_xbc + (size_t)r * CONVD + ch4) = acc;
}

__global__ void dtsp_kernel(const float* __restrict__ dtb)
{
    int idx = blockIdx.x * blockDim.x + threadIdx.x;
    if (idx >= NROWS * NH) return;
    int h = idx & 7;
    int r = idx >> 3;
    float v = g_zxbcdt[(size_t)r * DPROJ + (DPROJ - NH) + h] + dtb[h];
    g_dtsp[idx] = (v > 20.f) ? v : log1pf(__expf(v));
}

__global__ void acs_kernel(const float* __restrict__ A_log)
{
    __shared__ float sh[64];
    int id = blockIdx.x;
    int c  = id % NC;
    int bh = id / NC;
    int h  = bh % NH;
    int b  = bh / NH;
    int l  = threadIdx.x;
    float Ah = -expf(A_log[h]);
    sh[l] = g_dtsp[(size_t)(b * L_SZ + c * 64 + l) * NH + h] * Ah;
    __syncthreads();
    for (int off = 1; off < 64; off <<= 1) {
        float v = (l >= off) ? sh[l - off] : 0.f;
        __syncthreads();
        sh[l] += v;
        __syncthreads();
    }
    g_acs[(size_t)id * 64 + l] = sh[l];
    if (l == 63) g_cdec[id] = __expf(sh[63]);
}

/* ------------------------------------------------------------------ */
/* 64x64x64 tf32 tensor-core matmul from smem (8 warps, 4 tiles each)  */
/* D[m][n] = sum_k A[m][k] * B[n][k]; warp covers m16 x n32            */
/* ------------------------------------------------------------------ */
#define SR 68
#define SZT (64*SR)   /* 4352 floats */

__device__ __forceinline__ void mm64(const float* __restrict__ sA,
                                     const float* __restrict__ sB,
                                     int wm, int wn, int g, int tg,
                                     float acc[4][4])
{
#pragma unroll
    for (int k0 = 0; k0 < 64; k0 += 8) {
        uint32_t a0 = f2tf32(sA[(wm + g)     * SR + k0 + tg]);
        uint32_t a1 = f2tf32(sA[(wm + 8 + g) * SR + k0 + tg]);
        uint32_t a2 = f2tf32(sA[(wm + g)     * SR + k0 + 4 + tg]);
        uint32_t a3 = f2tf32(sA[(wm + 8 + g) * SR + k0 + 4 + tg]);
#pragma unroll
        for (int nt = 0; nt < 4; nt++) {
            uint32_t b0 = f2tf32(sB[(wn + nt * 8 + g) * SR + k0 + tg]);
            uint32_t b1 = f2tf32(sB[(wn + nt * 8 + g) * SR + k0 + 4 + tg]);
            mma_tf32(acc[nt], a0, a1, a2, a3, b0, b1);
        }
    }
}

/* ------------------------------------------------------------------ */
/* Chunk kernel v3: tensor-core SSD matmuls                            */
/* smem: sB, sBt, sC(=sM), sG, sXt, sXdt + sAcs/sDec/sDt               */
/* ------------------------------------------------------------------ */
extern __shared__ float smem[];
__global__ void __launch_bounds__(256, 2)
chunk_kernel(const float* __restrict__ Dp)
{
    float* sB   = smem;
    float* sBt  = smem + SZT;
    float* sC   = smem + 2*SZT;     /* reused as sM */
    float* sG   = smem + 3*SZT;
    float* sXt  = smem + 4*SZT;
    float* sXdt = smem + 5*SZT;
    float* sAcs = smem + 6*SZT;
    float* sDec = smem + 6*SZT + 64;
    float* sDt  = smem + 6*SZT + 128;
    float* sM   = sC;

    int bc = blockIdx.x;
    int b = bc / NC, c = bc % NC;
    int tid = threadIdx.x;
    int base = b * L_SZ + c * CHUNK;

    int warp = tid >> 5, lane = tid & 31;
    int g  = lane >> 2, tg = lane & 3;
    int wm = (warp >> 1) * 16;
    int wn = (warp & 1) * 32;

    /* load B[s][n], C[l][n], and Bt[n][s] */
    for (int i = tid; i < 1024; i += 256) {
        int l = i >> 4, n4 = (i & 15) * 4;
        const float* row = g_xbc + (size_t)(base + l) * CONVD + DINNER;
        float4 bv = *(const float4*)(row + n4);
        float4 cv = *(const float4*)(row + DSTATE + n4);
        *(float4*)&sB[l * SR + n4] = bv;
        *(float4*)&sC[l * SR + n4] = cv;
        sBt[(n4 + 0) * SR + l] = bv.x;
        sBt[(n4 + 1) * SR + l] = bv.y;
        sBt[(n4 + 2) * SR + l] = bv.z;
        sBt[(n4 + 3) * SR + l] = bv.w;
    }
    __syncthreads();

    /* G[l][s] = sum_n C[l][n] * B[s][n] */
    {
        float acc[4][4];
#pragma unroll
        for (int i = 0; i < 4; i++)
#pragma unroll
            for (int j = 0; j < 4; j++) acc[i][j] = 0.f;
        mm64(sC, sB, wm, wn, g, tg, acc);
#pragma unroll
        for (int nt = 0; nt < 4; nt++) {
            int cl = wn + nt * 8 + 2 * tg;
            sG[(wm + g)     * SR + cl]     = acc[nt][0];
            sG[(wm + g)     * SR + cl + 1] = acc[nt][1];
            sG[(wm + 8 + g) * SR + cl]     = acc[nt][2];
            sG[(wm + 8 + g) * SR + cl + 1] = acc[nt][3];
        }
    }
    __syncthreads();

    for (int h = 0; h < NH; h++) {
        if (tid < 64) {
            sDt[tid] = g_dtsp[(size_t)(base + tid) * NH + h];
            const float* ac = g_acs + ((size_t)(b * NH + h) * NC + c) * 64;
            float a = ac[tid];
            sAcs[tid] = a;
            sDec[tid] = __expf(ac[63] - a);
        }
        __syncthreads();

        /* M[l][s] (overwrites sC) */
        for (int i = tid; i < 4096; i += 256) {
            int l = i >> 6, s = i & 63;
            sM[l * SR + s] = (s <= l) ? sG[l * SR + s] * __expf(sAcs[l] - sAcs[s]) : 0.f;
        }
        /* Xt[p][s] = X[s][p]*dt[s]; Xdt[p][s] = Xt * dec[s] */
        for (int i = tid; i < 1024; i += 256) {
            int s = i >> 4, p4 = (i & 15) * 4;
            float4 xv = *(const float4*)(g_xbc + (size_t)(base + s) * CONVD + h * HD + p4);
            float dts = sDt[s], dec = sDec[s];
            float x0 = xv.x * dts, x1 = xv.y * dts, x2 = xv.z * dts, x3 = xv.w * dts;
            sXt[(p4 + 0) * SR + s] = x0;
            sXt[(p4 + 1) * SR + s] = x1;
            sXt[(p4 + 2) * SR + s] = x2;
            sXt[(p4 + 3) * SR + s] = x3;
            sXdt[(p4 + 0) * SR + s] = x0 * dec;
            sXdt[(p4 + 1) * SR + s] = x1 * dec;
            sXdt[(p4 + 2) * SR + s] = x2 * dec;
            sXdt[(p4 + 3) * SR + s] = x3 * dec;
        }
        __syncthreads();

        /* Y[l][p] = sum_s M[l][s]*Xt[p][s]  (+ Dp*X) */
        {
            float acc[4][4];
#pragma unroll
            for (int i = 0; i < 4; i++)
#pragma unroll
                for (int j = 0; j < 4; j++) acc[i][j] = 0.f;
            mm64(sM, sXt, wm, wn, g, tg, acc);
            float Dph = Dp[h];
            int r0 = base + wm + g, r1 = r0 + 8;
#pragma unroll
            for (int nt = 0; nt < 4; nt++) {
                int p = wn + nt * 8 + 2 * tg;
                float2 x0 = *(const float2*)(g_xbc + (size_t)r0 * CONVD + h * HD + p);
                float2 x1 = *(const float2*)(g_xbc + (size_t)r1 * CONVD + h * HD + p);
                *(float2*)(g_y + (size_t)r0 * DINNER + h * HD + p) =
                    make_float2(acc[nt][0] + Dph * x0.x, acc[nt][1] + Dph * x0.y);
                *(float2*)(g_y + (size_t)r1 * DINNER + h * HD + p) =
                    make_float2(acc[nt][2] + Dph * x1.x, acc[nt][3] + Dph * x1.y);
            }
        }
        /* states[n][p] = sum_l Bt[n][l]*Xdt[p][l] */
        {
            float acc[4][4];
#pragma unroll
            for (int i = 0; i < 4; i++)
#pragma unroll
                for (int j = 0; j < 4; j++) acc[i][j] = 0.f;
            mm64(sBt, sXdt, wm, wn, g, tg, acc);
            float* sp = g_states + (((size_t)(bc) * NH + h) << 12);
#pragma unroll
            for (int nt = 0; nt < 4; nt++) {
                int p = wn + nt * 8 + 2 * tg;
                *(float2*)(sp + (wm + g)     * 64 + p) = make_float2(acc[nt][0], acc[nt][1]);
                *(float2*)(sp + (wm + 8 + g) * 64 + p) = make_float2(acc[nt][2], acc[nt][3]);
            }
        }
        __syncthreads();
    }
}

/* sequential inter-chunk state recurrence (elementwise over [n][p])   */
__global__ void scan_kernel(void)
{
    int idx = blockIdx.x * blockDim.x + threadIdx.x;
    int e = idx & 4095;
    int h = (idx >> 12) & 7;
    int b = idx >> 15;
    float carry = 0.f;
    for (int c = 0; c < NC; c++) {
        size_t off = (((size_t)(b * NC + c) * NH + h) << 12) + e;
        g_prev[off] = carry;
        carry = carry * g_cdec[(b * NH + h) * NC + c] + g_states[off];
    }
}

/* Y_off: tensor-core C @ prev, scaled by exp(Acs), added into g_y     */
__global__ void __launch_bounds__(256)
yoff_kernel(void)
{
    __shared__ float sC[SZT];
    __shared__ float sPt[SZT];
    __shared__ float sE[64];
    int id = blockIdx.x;
    int h = id % NH;
    int c = (id / NH) % NC;
    int b = id / (NH * NC);
    int tid = threadIdx.x;
    int base = b * L_SZ + c * CHUNK;

    int warp = tid >> 5, lane = tid & 31;
    int g  = lane >> 2, tg = lane & 3;
    int wm = (warp >> 1) * 16;
    int wn = (warp & 1) * 32;

    const float* pv = g_prev + (((size_t)(b * NC + c) * NH + h) << 12);
    for (int i = tid; i < 1024; i += 256) {
        int n = i >> 4, p4 = (i & 15) * 4;
        float4 cv = *(const float4*)(g_xbc + (size_t)(base + n) * CONVD
                                     + DINNER + DSTATE + p4);
        *(float4*)&sC[n * SR + p4] = cv;
        float4 pvv = *(const float4*)(pv + n * 64 + p4);
        sPt[(p4 + 0) * SR + n] = pvv.x;
        sPt[(p4 + 1) * SR + n] = pvv.y;
        sPt[(p4 + 2) * SR + n] = pvv.z;
        sPt[(p4 + 3) * SR + n] = pvv.w;
    }
    if (tid < 64) sE[tid] = __expf(g_acs[((size_t)(b * NH + h) * NC + c) * 64 + tid]);
    __syncthreads();

    /* Yoff[l][p] = sum_n C[l][n]*Pt[p][n] */
    float acc[4][4];
#pragma unroll
    for (int i = 0; i < 4; i++)
#pragma unroll
        for (int j = 0; j < 4; j++) acc[i][j] = 0.f;
    mm64(sC, sPt, wm, wn, g, tg, acc);

    int r0 = base + wm + g, r1 = r0 + 8;
    float e0 = sE[wm + g], e1 = sE[wm + 8 + g];
#pragma unroll
    for (int nt = 0; nt < 4; nt++) {
        int p = wn + nt * 8 + 2 * tg;
        float2* y0 = (float2*)(g_y + (size_t)r0 * DINNER + h * HD + p);
        float2* y1 = (float2*)(g_y + (size_t)r1 * DINNER + h * HD + p);
        float2 v0 = *y0, v1 = *y1;
        v0.x += acc[nt][0] * e0;  v0.y += acc[nt][1] * e0;
        v1.x += acc[nt][2] * e1;  v1.y += acc[nt][3] * e1;
        *y0 = v0; *y1 = v1;
    }
}

/* u = y*silu(z); RMSNorm(u)*norm_w -> g_yn (tf32-rounded)             */
__global__ void gate_rms(const float* __restrict__ nw)
{
    __shared__ float red[256];
    int r = blockIdx.x, tid = threadIdx.x;
    const float* zrow = g_zxbcdt + (size_t)r * DPROJ;
    const float* yrow = g_y + (size_t)r * DINNER;
    float z0 = zrow[tid], z1 = zrow[tid + 256];
    float u0 = yrow[tid]       * (z0 / (1.f + __expf(-z0)));
    float u1 = yrow[tid + 256] * (z1 / (1.f + __expf(-z1)));
    red[tid] = u0 * u0 + u1 * u1;
    __syncthreads();
    for (int s = 128; s > 0; s >>= 1) {
        if (tid < s) red[tid] += red[tid + s];
        __syncthreads();
    }
    float scale = rsqrtf(red[0] / 512.f + 1e-12f);
    g_yn[(size_t)r * DINNER + tid]       = tf32r(u0 * scale * nw[tid]);
    g_yn[(size_t)r * DINNER + tid + 256] = tf32r(u1 * scale * nw[tid + 256]);
}

/* LayerNorm(a + res) * g + b                                          */
__global__ void ln_res(const float* __restrict__ a, const float* __restrict__ res,
                       const float* __restrict__ g, const float* __restrict__ bb,
                       float* __restrict__ out, int rnd)
{
    __shared__ float red[256];
    int r = blockIdx.x, tid = threadIdx.x;
    float x = a[(size_t)r * 256 + tid] + res[(size_t)r * 256 + tid];
    red[tid] = x;
    __syncthreads();
    for (int s = 128; s > 0; s >>= 1) {
        if (tid < s) red[tid] += red[tid + s];
        __syncthreads();
    }
    float mean = red[0] / 256.f;
    __syncthreads();
    float d = x - mean;
    red[tid] = d * d;
    __syncthreads();
    for (int s = 128; s > 0; s >>= 1) {
        if (tid < s) red[tid] += red[tid + s];
        __syncthreads();
    }
    float var = red[0] / 256.f;
    float v = d * rsqrtf(var + 1e-12f) * g[tid] + bb[tid];
    out[(size_t)r * 256 + tid] = rnd ? tf32r(v) : v;
}

/* ------------------------------------------------------------------ */
extern "C" void kernel_launch(void* const* d_in, const int* in_sizes, int n_in,
                              void* d_out, int out_size)
{
    const float* x       = (const float*)d_in[0];
    const float* in_w    = (const float*)d_in[1];
    const float* in_b    = (const float*)d_in[2];
    const float* conv_w  = (const float*)d_in[3];
    const float* conv_b  = (const float*)d_in[4];
    const float* dt_bias = (const float*)d_in[5];
    const float* A_log   = (const float*)d_in[6];
    const float* Dp      = (const float*)d_in[7];
    const float* norm_w  = (const float*)d_in[8];
    const float* out_w   = (const float*)d_in[9];
    const float* out_b   = (const float*)d_in[10];
    const float* ln_g    = (const float*)d_in[11];
    const float* ln_b    = (const float*)d_in[12];
    const float* fc1_w   = (const float*)d_in[13];
    const float* fc1_b   = (const float*)d_in[14];
    const float* fc2_w   = (const float*)d_in[15];
    const float* fc2_b   = (const float*)d_in[16];
    const float* fln_g   = (const float*)d_in[17];
    const float* fln_b   = (const float*)d_in[18];
    float* out = (float*)d_out;

    void *p;
    cudaGetSymbolAddress(&p, g_zxbcdt);  float* zx     = (float*)p;
    cudaGetSymbolAddress(&p, g_yn);      float* yn     = (float*)p;
    cudaGetSymbolAddress(&p, g_t256);    float* t256   = (float*)p;
    cudaGetSymbolAddress(&p, g_hidden);  float* hidden = (float*)p;
    cudaGetSymbolAddress(&p, g_h1);      float* h1     = (float*)p;
    cudaGetSymbolAddress(&p, g_xtf);     float* xtf    = (float*)p;
    cudaGetSymbolAddress(&p, g_wtf);     float* wtf    = (float*)p;

    static int chunk_smem = 6 * SZT * 4 + 3 * 64 * 4;   /* 105216 B */
    cudaFuncSetAttribute(chunk_kernel,
                         cudaFuncAttributeMaxDynamicSharedMemorySize, chunk_smem);
    cudaFuncSetAttribute(gemm_tf32,
                         cudaFuncAttributeMaxDynamicSharedMemorySize, 110592);

    /* 0. tf32 conversions */
    cvt_tf32<<<(NROWS*DMODEL + 255)/256, 256>>>(x, xtf, NROWS*DMODEL);
    cvt_tf32<<<(DPROJ*DMODEL + 255)/256, 256>>>(in_w,  wtf + W_IN_OFF,  DPROJ*DMODEL);
    cvt_tf32<<<(DMODEL*DINNER + 255)/256, 256>>>(out_w, wtf + W_OUT_OFF, DMODEL*DINNER);
    cvt_tf32<<<(DFFN*DMODEL + 255)/256, 256>>>(fc1_w,  wtf + W_FC1_OFF, DFFN*DMODEL);
    cvt_tf32<<<(DMODEL*DFFN + 255)/256, 256>>>(fc2_w,  wtf + W_FC2_OFF, DMODEL*DFFN);

    /* 1. in_proj */
    gemm_tf32<<<dim3((DPROJ + 127) / 128, NROWS / 128), 128, 110592>>>(
        xtf, wtf + W_IN_OFF, in_b, zx, NROWS, DPROJ, DMODEL, 0);
    /* 2-4 */
    conv_kernel<<<(NROWS * (CONVD/4) + 255) / 256, 256>>>(conv_w, conv_b);
    dtsp_kernel<<<(NROWS * NH + 255) / 256, 256>>>(dt_bias);
    acs_kernel<<<B_SZ * NH * NC, 64>>>(A_log);
    /* 5. intra-chunk (tensor-core) */
    chunk_kernel<<<B_SZ * NC, 256, chunk_smem>>>(Dp);
    /* 6. inter-chunk scan */
    scan_kernel<<<(B_SZ * NH * HD * DSTATE + 255) / 256, 256>>>();
    /* 7. Y_off (tensor-core) */
    yoff_kernel<<<B_SZ * NC * NH, 256>>>();
    /* 8. gate + RMSNorm */
    gate_rms<<<NROWS, 256>>>(norm_w);
    /* 9. out_proj */
    gemm_tf32<<<dim3(DMODEL / 128, NROWS / 128), 128, 110592>>>(
        yn, wtf + W_OUT_OFF, out_b, t256, NROWS, DMODEL, DINNER, 0);
    /* 10 */
    ln_res<<<NROWS, 256>>>(t256, x, ln_g, ln_b, hidden, 1);
    /* 11 */
    gemm_tf32<<<dim3(DFFN / 128, NROWS / 128), 128, 110592>>>(
        hidden, wtf + W_FC1_OFF, fc1_b, h1, NROWS, DFFN, DMODEL, 1);
    /* 12 */
    gemm_tf32<<<dim3(DMODEL / 128, NROWS / 128), 128, 110592>>>(
        h1, wtf + W_FC2_OFF, fc2_b, t256, NROWS, DMODEL, DFFN, 0);
    /* 13 */
    ln_res<<<NROWS, 256>>>(t256, hidden, fln_g, fln_b, out, 0);
}